// round 3
// baseline (speedup 1.0000x reference)
#include <cuda_runtime.h>
#include <math.h>

#define N_NODES 20000
#define N_EDGES 320000
#define IN_CH   256
#define HIDHEAD 256   // HEADS*HID
#define HEADS   8
#define HID     32
#define NCLS    16
#define ET_MAX  (N_EDGES + N_NODES)

// ---------------- scratch (device globals; allocation-free) ----------------
__device__ float g_h1  [(size_t)N_NODES * HIDHEAD];   // x @ W1
__device__ float g_h2  [(size_t)N_NODES * NCLS];      // layer2 pre-agg features
__device__ float g_as1 [N_NODES * HEADS];
__device__ float g_ad1 [N_NODES * HEADS];
__device__ float g_as2 [N_NODES];
__device__ float g_ad2 [N_NODES];
__device__ int   g_deg [N_NODES];
__device__ int   g_start[N_NODES + 1];
__device__ int   g_cursor[N_NODES];
__device__ int2  g_csr [ET_MAX];                      // {src, bitcast(ew)}

// ---------------- CSR build ----------------
__global__ void hist_k(const int* __restrict__ ei, int E, int ET) {
    int e = blockIdx.x * blockDim.x + threadIdx.x;
    if (e >= ET) return;
    int dst = (e < E) ? ei[E + e] : (e - E);
    atomicAdd(&g_deg[dst], 1);
}

// single-block scan: each thread owns a contiguous chunk
__global__ void scan_k(int n) {
    __shared__ int sh[1024];
    int tid = threadIdx.x;
    int chunk = (n + 1023) / 1024;
    int b = tid * chunk;
    int e = b + chunk; if (e > n) e = n;
    int s = 0;
    for (int i = b; i < e; i++) s += g_deg[i];
    sh[tid] = s;
    __syncthreads();
    for (int off = 1; off < 1024; off <<= 1) {
        int t = (tid >= off) ? sh[tid - off] : 0;
        __syncthreads();
        sh[tid] += t;
        __syncthreads();
    }
    int run = sh[tid] - s;  // exclusive prefix
    for (int i = b; i < e; i++) {
        g_start[i] = run;
        g_cursor[i] = run;
        run += g_deg[i];
    }
    if (tid == 1023) g_start[n] = sh[1023];
}

__global__ void scatter_k(const int* __restrict__ ei, const float* __restrict__ ew,
                          int E, int ET) {
    int e = blockIdx.x * blockDim.x + threadIdx.x;
    if (e >= ET) return;
    int src, dst; float w;
    if (e < E) { src = ei[e]; dst = ei[E + e]; w = ew[e]; }
    else       { src = e - E; dst = e - E;     w = 1.0f; }
    int pos = atomicAdd(&g_cursor[dst], 1);
    g_csr[pos] = make_int2(src, __float_as_int(w));
}

// ---------------- GEMM1 + fused att1 ----------------
// C[N,256] = A[N,256] @ B[256,256]; 128x128x8 tile, 256 threads, 8x8/thread,
// double-buffered smem. Epilogue computes as1/ad1: each thread's 8 cols lie in
// one head (8 | 32), reduce over the 4-lane tx-group with shfl_xor.
__global__ void sgemm_att_k(const float* __restrict__ A, const float* __restrict__ B,
                            float* __restrict__ C,
                            const float* __restrict__ asw, const float* __restrict__ adw,
                            int N) {
    __shared__ float As[2][8][132];
    __shared__ float Bs[2][8][132];
    int tid = threadIdx.x;
    int tx = tid & 15, ty = tid >> 4;
    int row0 = blockIdx.x * 128;
    int col0 = blockIdx.y * 128;
    float acc[8][8];
#pragma unroll
    for (int i = 0; i < 8; i++)
#pragma unroll
        for (int j = 0; j < 8; j++) acc[i][j] = 0.f;

    int ar = tid >> 1, akq = (tid & 1) * 4;
    int bk = tid >> 5, bcq = (tid & 31) * 4;
    bool arow_ok = (row0 + ar < N);

    // preload tile 0
    float4 av = make_float4(0.f, 0.f, 0.f, 0.f);
    if (arow_ok) av = *(const float4*)(A + (size_t)(row0 + ar) * 256 + akq);
    float4 bv = *(const float4*)(B + (size_t)bk * 256 + col0 + bcq);
    As[0][akq + 0][ar] = av.x; As[0][akq + 1][ar] = av.y;
    As[0][akq + 2][ar] = av.z; As[0][akq + 3][ar] = av.w;
    *(float4*)&Bs[0][bk][bcq] = bv;
    __syncthreads();

    int cur = 0;
    for (int kt = 0; kt < 256; kt += 8) {
        if (kt + 8 < 256) {
            av = make_float4(0.f, 0.f, 0.f, 0.f);
            if (arow_ok) av = *(const float4*)(A + (size_t)(row0 + ar) * 256 + kt + 8 + akq);
            bv = *(const float4*)(B + (size_t)(kt + 8 + bk) * 256 + col0 + bcq);
        }
#pragma unroll
        for (int k = 0; k < 8; k++) {
            float4 a0 = *(float4*)&As[cur][k][ty * 8];
            float4 a1 = *(float4*)&As[cur][k][ty * 8 + 4];
            float4 b0 = *(float4*)&Bs[cur][k][tx * 8];
            float4 b1 = *(float4*)&Bs[cur][k][tx * 8 + 4];
            float a[8] = {a0.x, a0.y, a0.z, a0.w, a1.x, a1.y, a1.z, a1.w};
            float b[8] = {b0.x, b0.y, b0.z, b0.w, b1.x, b1.y, b1.z, b1.w};
#pragma unroll
            for (int i = 0; i < 8; i++)
#pragma unroll
                for (int j = 0; j < 8; j++) acc[i][j] = fmaf(a[i], b[j], acc[i][j]);
        }
        if (kt + 8 < 256) {
            int nxt = cur ^ 1;
            As[nxt][akq + 0][ar] = av.x; As[nxt][akq + 1][ar] = av.y;
            As[nxt][akq + 2][ar] = av.z; As[nxt][akq + 3][ar] = av.w;
            *(float4*)&Bs[nxt][bk][bcq] = bv;
            __syncthreads();
            cur = nxt;
        }
    }

    // store C
#pragma unroll
    for (int i = 0; i < 8; i++) {
        int grow = row0 + ty * 8 + i;
        if (grow < N) {
            *(float4*)(C + (size_t)grow * 256 + col0 + tx * 8)     =
                make_float4(acc[i][0], acc[i][1], acc[i][2], acc[i][3]);
            *(float4*)(C + (size_t)grow * 256 + col0 + tx * 8 + 4) =
                make_float4(acc[i][4], acc[i][5], acc[i][6], acc[i][7]);
        }
    }

    // fused att1: head for this thread's cols
    int hg = (col0 >> 5) + (tx >> 2);          // global head 0..7
    int cq = (tx & 3) * 8;                     // col within head
    float as_r[8], ad_r[8];
#pragma unroll
    for (int j = 0; j < 8; j++) {
        as_r[j] = asw[hg * 32 + cq + j];
        ad_r[j] = adw[hg * 32 + cq + j];
    }
#pragma unroll
    for (int i = 0; i < 8; i++) {
        float ps = 0.f, pd = 0.f;
#pragma unroll
        for (int j = 0; j < 8; j++) {
            ps = fmaf(acc[i][j], as_r[j], ps);
            pd = fmaf(acc[i][j], ad_r[j], pd);
        }
        ps += __shfl_xor_sync(0xffffffffu, ps, 1);
        ps += __shfl_xor_sync(0xffffffffu, ps, 2);
        pd += __shfl_xor_sync(0xffffffffu, pd, 1);
        pd += __shfl_xor_sync(0xffffffffu, pd, 2);
        int grow = row0 + ty * 8 + i;
        if ((tx & 3) == 0 && grow < N) {
            g_as1[grow * HEADS + hg] = ps;
            g_ad1[grow * HEADS + hg] = pd;
        }
    }
}

// ---------------- layer-1 aggregation fused with GEMM2 + att2 ----------------
__global__ void agg1_k(const float* __restrict__ b1, const float* __restrict__ W2,
                       const float* __restrict__ as2w, const float* __restrict__ ad2w,
                       int N) {
    __shared__ float sW2t[NCLS * 256];   // [m][c], 16KB
    __shared__ float sas2[NCLS], sad2[NCLS];
    int tid = threadIdx.x;
    for (int i = tid; i < 256 * NCLS; i += 256) {
        int c = i >> 4, m = i & 15;
        sW2t[m * 256 + c] = W2[i];
    }
    if (tid < NCLS) { sas2[tid] = as2w[tid]; sad2[tid] = ad2w[tid]; }
    __syncthreads();

    int warp = blockIdx.x * 8 + (tid >> 5);
    if (warp >= N) return;
    int lane = tid & 31;
    int s = g_start[warp], e = g_start[warp + 1];
    float adv = (lane < HEADS) ? g_ad1[warp * HEADS + lane] : 0.f;
    int h0 = lane >> 3;
    bool is_head = (lane < HEADS);

    float4 acc0 = make_float4(0.f, 0.f, 0.f, 0.f);
    float4 acc1 = make_float4(0.f, 0.f, 0.f, 0.f);
    float den = 0.f;

    int i = s;
    // unroll-2: two independent edge gathers in flight
    for (; i + 1 < e; i += 2) {
        int2 ea = g_csr[i];
        int2 eb = g_csr[i + 1];
        int sa = ea.x, sb = eb.x;
        float wa = __int_as_float(ea.y), wb = __int_as_float(eb.y);
        float asa = 0.f, asb = 0.f;
        if (is_head) {
            asa = g_as1[sa * HEADS + lane];
            asb = g_as1[sb * HEADS + lane];
        }
        const float4* hpA = (const float4*)(g_h1 + (size_t)sa * HIDHEAD);
        const float4* hpB = (const float4*)(g_h1 + (size_t)sb * HIDHEAD);
        float4 va0 = hpA[lane], va1 = hpA[lane + 32];
        float4 vb0 = hpB[lane], vb1 = hpB[lane + 32];
        float ta = 0.f, tb = 0.f;
        if (is_head) {
            float u = asa + adv; u = (u > 0.f ? u : 0.2f * u) * wa; ta = __expf(u);
            float v = asb + adv; v = (v > 0.f ? v : 0.2f * v) * wb; tb = __expf(v);
        }
        den += ta + tb;
        float wA0 = __shfl_sync(0xffffffffu, ta, h0);
        float wA1 = __shfl_sync(0xffffffffu, ta, 4 + h0);
        float wB0 = __shfl_sync(0xffffffffu, tb, h0);
        float wB1 = __shfl_sync(0xffffffffu, tb, 4 + h0);
        acc0.x = fmaf(wA0, va0.x, acc0.x); acc0.y = fmaf(wA0, va0.y, acc0.y);
        acc0.z = fmaf(wA0, va0.z, acc0.z); acc0.w = fmaf(wA0, va0.w, acc0.w);
        acc1.x = fmaf(wA1, va1.x, acc1.x); acc1.y = fmaf(wA1, va1.y, acc1.y);
        acc1.z = fmaf(wA1, va1.z, acc1.z); acc1.w = fmaf(wA1, va1.w, acc1.w);
        acc0.x = fmaf(wB0, vb0.x, acc0.x); acc0.y = fmaf(wB0, vb0.y, acc0.y);
        acc0.z = fmaf(wB0, vb0.z, acc0.z); acc0.w = fmaf(wB0, vb0.w, acc0.w);
        acc1.x = fmaf(wB1, vb1.x, acc1.x); acc1.y = fmaf(wB1, vb1.y, acc1.y);
        acc1.z = fmaf(wB1, vb1.z, acc1.z); acc1.w = fmaf(wB1, vb1.w, acc1.w);
    }
    if (i < e) {
        int2 ea = g_csr[i];
        int sa = ea.x;
        float wa = __int_as_float(ea.y);
        float ta = 0.f;
        if (is_head) {
            float u = g_as1[sa * HEADS + lane] + adv;
            u = (u > 0.f ? u : 0.2f * u) * wa;
            ta = __expf(u);
        }
        den += ta;
        const float4* hpA = (const float4*)(g_h1 + (size_t)sa * HIDHEAD);
        float4 va0 = hpA[lane], va1 = hpA[lane + 32];
        float wA0 = __shfl_sync(0xffffffffu, ta, h0);
        float wA1 = __shfl_sync(0xffffffffu, ta, 4 + h0);
        acc0.x = fmaf(wA0, va0.x, acc0.x); acc0.y = fmaf(wA0, va0.y, acc0.y);
        acc0.z = fmaf(wA0, va0.z, acc0.z); acc0.w = fmaf(wA0, va0.w, acc0.w);
        acc1.x = fmaf(wA1, va1.x, acc1.x); acc1.y = fmaf(wA1, va1.y, acc1.y);
        acc1.z = fmaf(wA1, va1.z, acc1.z); acc1.w = fmaf(wA1, va1.w, acc1.w);
    }

    // finalize: softmax divide, bias, ELU
    float d0 = __shfl_sync(0xffffffffu, den, h0);
    float d1 = __shfl_sync(0xffffffffu, den, 4 + h0);
    float inv0 = 1.f / (d0 + 1e-16f);
    float inv1 = 1.f / (d1 + 1e-16f);
    float4 bb0 = ((const float4*)b1)[lane];
    float4 bb1 = ((const float4*)b1)[lane + 32];
    float o[8];
    o[0] = acc0.x * inv0 + bb0.x;  o[1] = acc0.y * inv0 + bb0.y;
    o[2] = acc0.z * inv0 + bb0.z;  o[3] = acc0.w * inv0 + bb0.w;
    o[4] = acc1.x * inv1 + bb1.x;  o[5] = acc1.y * inv1 + bb1.y;
    o[6] = acc1.z * inv1 + bb1.z;  o[7] = acc1.w * inv1 + bb1.w;
#pragma unroll
    for (int j = 0; j < 8; j++) o[j] = (o[j] > 0.f) ? o[j] : (__expf(o[j]) - 1.f);

    // GEMM2 partials against smem-resident W2^T
    float h2p[NCLS];
#pragma unroll
    for (int m = 0; m < NCLS; m++) {
        float4 wv0 = *(const float4*)&sW2t[m * 256 + lane * 4];
        float4 wv1 = *(const float4*)&sW2t[m * 256 + 128 + lane * 4];
        h2p[m] = o[0] * wv0.x + o[1] * wv0.y + o[2] * wv0.z + o[3] * wv0.w
               + o[4] * wv1.x + o[5] * wv1.y + o[6] * wv1.z + o[7] * wv1.w;
    }
#pragma unroll
    for (int off = 16; off >= 1; off >>= 1)
#pragma unroll
        for (int m = 0; m < NCLS; m++)
            h2p[m] += __shfl_xor_sync(0xffffffffu, h2p[m], off);

    float s2 = 0.f, d2 = 0.f;
#pragma unroll
    for (int m = 0; m < NCLS; m++) {
        s2 = fmaf(h2p[m], sas2[m], s2);
        d2 = fmaf(h2p[m], sad2[m], d2);
    }
    if (lane == 0) { g_as2[warp] = s2; g_ad2[warp] = d2; }

    float sel = h2p[0];
#pragma unroll
    for (int m = 1; m < NCLS; m++) sel = (lane == m) ? h2p[m] : sel;
    if (lane < NCLS) g_h2[warp * NCLS + lane] = sel;
}

// ---------------- layer-2 softmax aggregation (1 warp / dst node) ----------------
__global__ void agg2_k(const float* __restrict__ b2, float* __restrict__ out, int N) {
    int warp = (blockIdx.x * blockDim.x + threadIdx.x) >> 5;
    if (warp >= N) return;
    int lane = threadIdx.x & 31;
    int s = g_start[warp], e = g_start[warp + 1];
    float adv = g_ad2[warp];
    bool lo = (lane < NCLS);

    float acc = 0.f, den = 0.f;
    int i = s;
    for (; i + 1 < e; i += 2) {
        int2 ea = g_csr[i];
        int2 eb = g_csr[i + 1];
        float la = g_as2[ea.x] + adv;
        float lb = g_as2[eb.x] + adv;
        float fa = lo ? g_h2[(size_t)ea.x * NCLS + lane] : 0.f;
        float fb = lo ? g_h2[(size_t)eb.x * NCLS + lane] : 0.f;
        la = (la > 0.f ? la : 0.2f * la) * __int_as_float(ea.y);
        lb = (lb > 0.f ? lb : 0.2f * lb) * __int_as_float(eb.y);
        float xa = __expf(la), xb = __expf(lb);
        den += xa + xb;
        acc = fmaf(xa, fa, acc);
        acc = fmaf(xb, fb, acc);
    }
    if (i < e) {
        int2 ea = g_csr[i];
        float la = g_as2[ea.x] + adv;
        la = (la > 0.f ? la : 0.2f * la) * __int_as_float(ea.y);
        float xa = __expf(la);
        den += xa;
        if (lo) acc = fmaf(xa, g_h2[(size_t)ea.x * NCLS + lane], acc);
    }
    if (lo) out[(size_t)warp * NCLS + lane] = acc / (den + 1e-16f) + b2[lane];
}

// ---------------- launch ----------------
extern "C" void kernel_launch(void* const* d_in, const int* in_sizes, int n_in,
                              void* d_out, int out_size) {
    const float* x   = (const float*)d_in[0];
    const int*   ei  = (const int*)  d_in[1];
    const float* ew  = (const float*)d_in[2];
    const float* W1  = (const float*)d_in[3];
    const float* as1 = (const float*)d_in[4];
    const float* ad1 = (const float*)d_in[5];
    const float* b1  = (const float*)d_in[6];
    const float* W2  = (const float*)d_in[7];
    const float* as2 = (const float*)d_in[8];
    const float* ad2 = (const float*)d_in[9];
    const float* b2  = (const float*)d_in[10];
    float* out = (float*)d_out;

    int N  = in_sizes[0] / IN_CH;     // 20000
    int E  = in_sizes[2];             // 320000
    int ET = E + N;

    float *h1;
    void *degp;
    cudaGetSymbolAddress((void**)&h1, g_h1);
    cudaGetSymbolAddress(&degp, g_deg);

    // --- CSR build ---
    cudaMemsetAsync(degp, 0, (size_t)N * sizeof(int));
    hist_k<<<(ET + 255) / 256, 256>>>(ei, E, ET);
    scan_k<<<1, 1024>>>(N);
    scatter_k<<<(ET + 255) / 256, 256>>>(ei, ew, E, ET);

    // --- layer 1 (GEMM + att1 fused) ---
    {
        dim3 grid((N + 127) / 128, 2);
        sgemm_att_k<<<grid, 256>>>(x, W1, h1, as1, ad1, N);
    }
    agg1_k<<<(N + 7) / 8, 256>>>(b1, W2, as2, ad2, N);   // agg1 + GEMM2 + att2

    // --- layer 2 ---
    agg2_k<<<(N + 7) / 8, 256>>>(b2, out, N);
}

// round 4
// speedup vs baseline: 1.3226x; 1.3226x over previous
#include <cuda_runtime.h>
#include <cuda_bf16.h>
#include <math.h>
#include <stdint.h>

#define N_NODES 20000
#define N_EDGES 320000
#define IN_CH   256
#define HIDHEAD 256
#define HEADS   8
#define HID     32
#define NCLS    16
#define ET_MAX  (N_EDGES + N_NODES)

// ---------------- scratch ----------------
__device__ float g_h1  [(size_t)N_NODES * HIDHEAD];
__device__ float g_h2  [(size_t)N_NODES * NCLS];
__device__ float g_as1 [N_NODES * HEADS];
__device__ float g_ad1 [N_NODES * HEADS];
__device__ float g_as2 [N_NODES];
__device__ float g_ad2 [N_NODES];
__device__ int   g_deg [N_NODES];
__device__ int   g_start[N_NODES + 1];
__device__ int   g_cursor[N_NODES];
__device__ int2  g_csr [ET_MAX];
__device__ __nv_bfloat16 g_xh[(size_t)N_NODES * IN_CH];
__device__ __nv_bfloat16 g_xl[(size_t)N_NODES * IN_CH];
__device__ __nv_bfloat16 g_wh[IN_CH * HIDHEAD];
__device__ __nv_bfloat16 g_wl[IN_CH * HIDHEAD];

// ---------------- CSR build ----------------
__global__ void hist_k(const int* __restrict__ ei, int E, int ET) {
    int e = blockIdx.x * blockDim.x + threadIdx.x;
    if (e >= ET) return;
    int dst = (e < E) ? ei[E + e] : (e - E);
    atomicAdd(&g_deg[dst], 1);
}

__global__ void scan_k(int n) {
    __shared__ int sh[1024];
    int tid = threadIdx.x;
    int chunk = (n + 1023) / 1024;
    int b = tid * chunk;
    int e = b + chunk; if (e > n) e = n;
    int s = 0;
    for (int i = b; i < e; i++) s += g_deg[i];
    sh[tid] = s;
    __syncthreads();
    for (int off = 1; off < 1024; off <<= 1) {
        int t = (tid >= off) ? sh[tid - off] : 0;
        __syncthreads();
        sh[tid] += t;
        __syncthreads();
    }
    int run = sh[tid] - s;
    for (int i = b; i < e; i++) {
        g_start[i] = run;
        g_cursor[i] = run;
        run += g_deg[i];
    }
    if (tid == 1023) g_start[n] = sh[1023];
}

__global__ void scatter_k(const int* __restrict__ ei, const float* __restrict__ ew,
                          int E, int ET) {
    int e = blockIdx.x * blockDim.x + threadIdx.x;
    if (e >= ET) return;
    int src, dst; float w;
    if (e < E) { src = ei[e]; dst = ei[E + e]; w = ew[e]; }
    else       { src = e - E; dst = e - E;     w = 1.0f; }
    int pos = atomicAdd(&g_cursor[dst], 1);
    g_csr[pos] = make_int2(src, __float_as_int(w));
}

// ---------------- fp32 -> bf16 hi/lo split ----------------
__global__ void conv_k(const float4* __restrict__ src, uint2* __restrict__ hp,
                       uint2* __restrict__ lp, int n4) {
    int i = blockIdx.x * blockDim.x + threadIdx.x;
    if (i >= n4) return;
    float4 v = src[i];
    __nv_bfloat162 h0 = __floats2bfloat162_rn(v.x, v.y);
    __nv_bfloat162 h1 = __floats2bfloat162_rn(v.z, v.w);
    __nv_bfloat162 l0 = __floats2bfloat162_rn(v.x - __low2float(h0), v.y - __high2float(h0));
    __nv_bfloat162 l1 = __floats2bfloat162_rn(v.z - __low2float(h1), v.w - __high2float(h1));
    uint2 uh, ul;
    uh.x = *reinterpret_cast<unsigned*>(&h0);
    uh.y = *reinterpret_cast<unsigned*>(&h1);
    ul.x = *reinterpret_cast<unsigned*>(&l0);
    ul.y = *reinterpret_cast<unsigned*>(&l1);
    hp[i] = uh;
    lp[i] = ul;
}

// ---------------- mma helpers ----------------
__device__ __forceinline__ void mma16816(float* c, const uint32_t* a, const uint32_t* b) {
    asm volatile("mma.sync.aligned.m16n8k16.row.col.f32.bf16.bf16.f32 "
        "{%0,%1,%2,%3}, {%4,%5,%6,%7}, {%8,%9}, {%0,%1,%2,%3};"
        : "+f"(c[0]), "+f"(c[1]), "+f"(c[2]), "+f"(c[3])
        : "r"(a[0]), "r"(a[1]), "r"(a[2]), "r"(a[3]), "r"(b[0]), "r"(b[1]));
}
__device__ __forceinline__ void ldsm4(uint32_t* r, uint32_t a) {
    asm volatile("ldmatrix.sync.aligned.m8n8.x4.shared.b16 {%0,%1,%2,%3}, [%4];"
        : "=r"(r[0]), "=r"(r[1]), "=r"(r[2]), "=r"(r[3]) : "r"(a));
}
__device__ __forceinline__ void ldsm4t(uint32_t* r, uint32_t a) {
    asm volatile("ldmatrix.sync.aligned.m8n8.x4.trans.shared.b16 {%0,%1,%2,%3}, [%4];"
        : "=r"(r[0]), "=r"(r[1]), "=r"(r[2]), "=r"(r[3]) : "r"(a));
}

// ---------------- GEMM1 (bf16 split-3 tensor core) + fused att1 ----------------
// C[N,256] = X[N,256] @ W[256,256]; 128x128 block tile, 8 warps (4m x 2n),
// warp tile 32x64, k-step 16, double-buffered smem.
// smem A: stage*12288 + d*6144 + row*48 + chunk*16      (48B row pad: LDSM conflict-free)
// smem B: 24576 + stage*8192 + d*4096 + k*256 + (c ^ (k&7))*16
__global__ __launch_bounds__(256, 2)
void mma_gemm_att_k(const __nv_bfloat16* __restrict__ Ah, const __nv_bfloat16* __restrict__ Al,
                    const __nv_bfloat16* __restrict__ Bh, const __nv_bfloat16* __restrict__ Bl,
                    float* __restrict__ C,
                    const float* __restrict__ asw, const float* __restrict__ adw, int N) {
    __shared__ __align__(16) unsigned char smem[40960];
    const uint32_t sb = (uint32_t)__cvta_generic_to_shared(smem);

    int tid = threadIdx.x;
    int wid = tid >> 5, lane = tid & 31;
    int wm = wid & 3, wn = wid >> 2;
    int row0 = blockIdx.x * 128;
    int col0 = blockIdx.y * 128;

    float acc[2][8][4];
#pragma unroll
    for (int mi = 0; mi < 2; mi++)
#pragma unroll
        for (int ni = 0; ni < 8; ni++)
#pragma unroll
            for (int q = 0; q < 4; q++) acc[mi][ni][q] = 0.f;

    // per-thread load assignment
    int d = tid >> 7;                 // 0 = hi plane, 1 = lo plane
    int ar = tid & 127;
    int arow = row0 + ar;
    bool aok = (arow < N);
    const __nv_bfloat16* Asrc = (d ? Al : Ah) + (size_t)(aok ? arow : 0) * 256;
    uint32_t sA = (uint32_t)d * 6144 + (uint32_t)ar * 48;

    int bq = tid & 127;
    int bk = bq >> 3;
    int bc = (bq & 7) * 2;
    const __nv_bfloat16* Bsrc = (d ? Bl : Bh) + (size_t)bk * 256 + col0 + bc * 8;
    uint32_t sB0 = 24576u + (uint32_t)d * 4096 + (uint32_t)bk * 256 + (uint32_t)((bc ^ (bk & 7)) * 16);
    uint32_t sB1 = 24576u + (uint32_t)d * 4096 + (uint32_t)bk * 256 + (uint32_t)(((bc + 1) ^ (bk & 7)) * 16);

    // fragment smem addresses (stage-relative)
    uint32_t aoff[2][2];
#pragma unroll
    for (int dd = 0; dd < 2; dd++)
#pragma unroll
        for (int mi = 0; mi < 2; mi++)
            aoff[dd][mi] = (uint32_t)dd * 6144 +
                           (uint32_t)(wm * 32 + mi * 16 + (lane & 15)) * 48 +
                           (uint32_t)(lane >> 4) * 16;
    uint32_t boff[2][4];
#pragma unroll
    for (int dd = 0; dd < 2; dd++)
#pragma unroll
        for (int p = 0; p < 4; p++) {
            int kk = lane & 15;
            int cc = wn * 8 + p * 2 + (lane >> 4);
            boff[dd][p] = 24576u + (uint32_t)dd * 4096 + (uint32_t)kk * 256 +
                          (uint32_t)((cc ^ (kk & 7)) * 16);
        }

    // preload k-step 0
    uint4 ra0 = make_uint4(0,0,0,0), ra1 = make_uint4(0,0,0,0);
    if (aok) { ra0 = *(const uint4*)(Asrc); ra1 = *(const uint4*)(Asrc + 8); }
    uint4 rb0 = *(const uint4*)(Bsrc);
    uint4 rb1 = *(const uint4*)(Bsrc + 8);
    *(uint4*)(smem + sA)      = ra0;
    *(uint4*)(smem + sA + 16) = ra1;
    *(uint4*)(smem + sB0)     = rb0;
    *(uint4*)(smem + sB1)     = rb1;
    __syncthreads();

    uint32_t stA = 0, stB = 0;
    for (int kt = 0; kt < 16; kt++) {
        if (kt < 15) {
            if (aok) {
                ra0 = *(const uint4*)(Asrc + (kt + 1) * 16);
                ra1 = *(const uint4*)(Asrc + (kt + 1) * 16 + 8);
            }
            rb0 = *(const uint4*)(Bsrc + (size_t)(kt + 1) * 16 * 256);
            rb1 = *(const uint4*)(Bsrc + (size_t)(kt + 1) * 16 * 256 + 8);
        }

        uint32_t ah[2][4], al[2][4];
#pragma unroll
        for (int mi = 0; mi < 2; mi++) {
            ldsm4(ah[mi], sb + stA + aoff[0][mi]);
            ldsm4(al[mi], sb + stA + aoff[1][mi]);
        }
#pragma unroll
        for (int p = 0; p < 4; p++) {
            uint32_t bh[4], bl[4];
            ldsm4t(bh, sb + stB + boff[0][p]);
            ldsm4t(bl, sb + stB + boff[1][p]);
#pragma unroll
            for (int mi = 0; mi < 2; mi++) {
                // n-tile 2p: frags (bh[0],bh[1]) / (bl[0],bl[1])
                mma16816(acc[mi][p * 2],     ah[mi], bh);       // hi*hi
                mma16816(acc[mi][p * 2],     ah[mi], bl);       // hi*lo
                mma16816(acc[mi][p * 2],     al[mi], bh);       // lo*hi
                // n-tile 2p+1: frags (bh[2],bh[3]) / (bl[2],bl[3])
                mma16816(acc[mi][p * 2 + 1], ah[mi], bh + 2);
                mma16816(acc[mi][p * 2 + 1], ah[mi], bl + 2);
                mma16816(acc[mi][p * 2 + 1], al[mi], bh + 2);
            }
        }

        if (kt < 15) {
            uint32_t nstA = stA ^ 12288u, nstB = stB ^ 8192u;
            *(uint4*)(smem + nstA + sA)      = ra0;
            *(uint4*)(smem + nstA + sA + 16) = ra1;
            *(uint4*)(smem + nstB + sB0)     = rb0;
            *(uint4*)(smem + nstB + sB1)     = rb1;
            __syncthreads();
            stA = nstA; stB = nstB;
        }
    }

    // store C
    int rbase = row0 + wm * 32 + (lane >> 2);
    int cbase = col0 + wn * 64 + (lane & 3) * 2;
#pragma unroll
    for (int mi = 0; mi < 2; mi++)
#pragma unroll
        for (int ni = 0; ni < 8; ni++) {
            int r = rbase + mi * 16;
            int c = cbase + ni * 8;
            if (r < N)
                *(float2*)(C + (size_t)r * 256 + c) = make_float2(acc[mi][ni][0], acc[mi][ni][1]);
            if (r + 8 < N)
                *(float2*)(C + (size_t)(r + 8) * 256 + c) = make_float2(acc[mi][ni][2], acc[mi][ni][3]);
        }

    // fused att1
    int hg0 = (col0 >> 5) + wn * 2;
    float asr[2][8], adr[2][8];
#pragma unroll
    for (int h = 0; h < 2; h++)
#pragma unroll
        for (int q = 0; q < 4; q++) {
            int c = (hg0 + h) * 32 + q * 8 + (lane & 3) * 2;
            asr[h][q * 2]     = asw[c];
            asr[h][q * 2 + 1] = asw[c + 1];
            adr[h][q * 2]     = adw[c];
            adr[h][q * 2 + 1] = adw[c + 1];
        }
#pragma unroll
    for (int mi = 0; mi < 2; mi++)
#pragma unroll
        for (int half = 0; half < 2; half++) {
            float ps0 = 0.f, pd0 = 0.f, ps1 = 0.f, pd1 = 0.f;
#pragma unroll
            for (int q = 0; q < 4; q++) {
                float v0 = acc[mi][q][half * 2], v1 = acc[mi][q][half * 2 + 1];
                ps0 = fmaf(v0, asr[0][q * 2], ps0); ps0 = fmaf(v1, asr[0][q * 2 + 1], ps0);
                pd0 = fmaf(v0, adr[0][q * 2], pd0); pd0 = fmaf(v1, adr[0][q * 2 + 1], pd0);
                float u0 = acc[mi][4 + q][half * 2], u1 = acc[mi][4 + q][half * 2 + 1];
                ps1 = fmaf(u0, asr[1][q * 2], ps1); ps1 = fmaf(u1, asr[1][q * 2 + 1], ps1);
                pd1 = fmaf(u0, adr[1][q * 2], pd1); pd1 = fmaf(u1, adr[1][q * 2 + 1], pd1);
            }
            ps0 += __shfl_xor_sync(0xffffffffu, ps0, 1); ps0 += __shfl_xor_sync(0xffffffffu, ps0, 2);
            pd0 += __shfl_xor_sync(0xffffffffu, pd0, 1); pd0 += __shfl_xor_sync(0xffffffffu, pd0, 2);
            ps1 += __shfl_xor_sync(0xffffffffu, ps1, 1); ps1 += __shfl_xor_sync(0xffffffffu, ps1, 2);
            pd1 += __shfl_xor_sync(0xffffffffu, pd1, 1); pd1 += __shfl_xor_sync(0xffffffffu, pd1, 2);
            int r = row0 + wm * 32 + mi * 16 + half * 8 + (lane >> 2);
            if ((lane & 3) == 0 && r < N) {
                g_as1[r * HEADS + hg0]     = ps0;
                g_ad1[r * HEADS + hg0]     = pd0;
                g_as1[r * HEADS + hg0 + 1] = ps1;
                g_ad1[r * HEADS + hg0 + 1] = pd1;
            }
        }
}

// ---------------- layer-1 aggregation fused with GEMM2 + att2 ----------------
__global__ void agg1_k(const float* __restrict__ b1, const float* __restrict__ W2,
                       const float* __restrict__ as2w, const float* __restrict__ ad2w,
                       int N) {
    __shared__ float sW2t[NCLS * 256];
    __shared__ float sas2[NCLS], sad2[NCLS];
    int tid = threadIdx.x;
    for (int i = tid; i < 256 * NCLS; i += 256) {
        int c = i >> 4, m = i & 15;
        sW2t[m * 256 + c] = W2[i];
    }
    if (tid < NCLS) { sas2[tid] = as2w[tid]; sad2[tid] = ad2w[tid]; }
    __syncthreads();

    int warp = blockIdx.x * 8 + (tid >> 5);
    if (warp >= N) return;
    int lane = tid & 31;
    int s = g_start[warp], e = g_start[warp + 1];
    float adv = (lane < HEADS) ? g_ad1[warp * HEADS + lane] : 0.f;
    int h0 = lane >> 3;
    bool is_head = (lane < HEADS);

    float4 acc0 = make_float4(0.f, 0.f, 0.f, 0.f);
    float4 acc1 = make_float4(0.f, 0.f, 0.f, 0.f);
    float den = 0.f;

    int i = s;
    for (; i + 1 < e; i += 2) {
        int2 ea = g_csr[i];
        int2 eb = g_csr[i + 1];
        int sa = ea.x, sb_ = eb.x;
        float wa = __int_as_float(ea.y), wb = __int_as_float(eb.y);
        float asa = 0.f, asb = 0.f;
        if (is_head) {
            asa = g_as1[sa * HEADS + lane];
            asb = g_as1[sb_ * HEADS + lane];
        }
        const float4* hpA = (const float4*)(g_h1 + (size_t)sa * HIDHEAD);
        const float4* hpB = (const float4*)(g_h1 + (size_t)sb_ * HIDHEAD);
        float4 va0 = hpA[lane], va1 = hpA[lane + 32];
        float4 vb0 = hpB[lane], vb1 = hpB[lane + 32];
        float ta = 0.f, tb = 0.f;
        if (is_head) {
            float u = asa + adv; u = (u > 0.f ? u : 0.2f * u) * wa; ta = __expf(u);
            float v = asb + adv; v = (v > 0.f ? v : 0.2f * v) * wb; tb = __expf(v);
        }
        den += ta + tb;
        float wA0 = __shfl_sync(0xffffffffu, ta, h0);
        float wA1 = __shfl_sync(0xffffffffu, ta, 4 + h0);
        float wB0 = __shfl_sync(0xffffffffu, tb, h0);
        float wB1 = __shfl_sync(0xffffffffu, tb, 4 + h0);
        acc0.x = fmaf(wA0, va0.x, acc0.x); acc0.y = fmaf(wA0, va0.y, acc0.y);
        acc0.z = fmaf(wA0, va0.z, acc0.z); acc0.w = fmaf(wA0, va0.w, acc0.w);
        acc1.x = fmaf(wA1, va1.x, acc1.x); acc1.y = fmaf(wA1, va1.y, acc1.y);
        acc1.z = fmaf(wA1, va1.z, acc1.z); acc1.w = fmaf(wA1, va1.w, acc1.w);
        acc0.x = fmaf(wB0, vb0.x, acc0.x); acc0.y = fmaf(wB0, vb0.y, acc0.y);
        acc0.z = fmaf(wB0, vb0.z, acc0.z); acc0.w = fmaf(wB0, vb0.w, acc0.w);
        acc1.x = fmaf(wB1, vb1.x, acc1.x); acc1.y = fmaf(wB1, vb1.y, acc1.y);
        acc1.z = fmaf(wB1, vb1.z, acc1.z); acc1.w = fmaf(wB1, vb1.w, acc1.w);
    }
    if (i < e) {
        int2 ea = g_csr[i];
        int sa = ea.x;
        float wa = __int_as_float(ea.y);
        float ta = 0.f;
        if (is_head) {
            float u = g_as1[sa * HEADS + lane] + adv;
            u = (u > 0.f ? u : 0.2f * u) * wa;
            ta = __expf(u);
        }
        den += ta;
        const float4* hpA = (const float4*)(g_h1 + (size_t)sa * HIDHEAD);
        float4 va0 = hpA[lane], va1 = hpA[lane + 32];
        float wA0 = __shfl_sync(0xffffffffu, ta, h0);
        float wA1 = __shfl_sync(0xffffffffu, ta, 4 + h0);
        acc0.x = fmaf(wA0, va0.x, acc0.x); acc0.y = fmaf(wA0, va0.y, acc0.y);
        acc0.z = fmaf(wA0, va0.z, acc0.z); acc0.w = fmaf(wA0, va0.w, acc0.w);
        acc1.x = fmaf(wA1, va1.x, acc1.x); acc1.y = fmaf(wA1, va1.y, acc1.y);
        acc1.z = fmaf(wA1, va1.z, acc1.z); acc1.w = fmaf(wA1, va1.w, acc1.w);
    }

    float d0 = __shfl_sync(0xffffffffu, den, h0);
    float d1 = __shfl_sync(0xffffffffu, den, 4 + h0);
    float inv0 = 1.f / (d0 + 1e-16f);
    float inv1 = 1.f / (d1 + 1e-16f);
    float4 bb0 = ((const float4*)b1)[lane];
    float4 bb1 = ((const float4*)b1)[lane + 32];
    float o[8];
    o[0] = acc0.x * inv0 + bb0.x;  o[1] = acc0.y * inv0 + bb0.y;
    o[2] = acc0.z * inv0 + bb0.z;  o[3] = acc0.w * inv0 + bb0.w;
    o[4] = acc1.x * inv1 + bb1.x;  o[5] = acc1.y * inv1 + bb1.y;
    o[6] = acc1.z * inv1 + bb1.z;  o[7] = acc1.w * inv1 + bb1.w;
#pragma unroll
    for (int j = 0; j < 8; j++) o[j] = (o[j] > 0.f) ? o[j] : (__expf(o[j]) - 1.f);

    float h2p[NCLS];
#pragma unroll
    for (int m = 0; m < NCLS; m++) {
        float4 wv0 = *(const float4*)&sW2t[m * 256 + lane * 4];
        float4 wv1 = *(const float4*)&sW2t[m * 256 + 128 + lane * 4];
        h2p[m] = o[0] * wv0.x + o[1] * wv0.y + o[2] * wv0.z + o[3] * wv0.w
               + o[4] * wv1.x + o[5] * wv1.y + o[6] * wv1.z + o[7] * wv1.w;
    }
#pragma unroll
    for (int off = 16; off >= 1; off >>= 1)
#pragma unroll
        for (int m = 0; m < NCLS; m++)
            h2p[m] += __shfl_xor_sync(0xffffffffu, h2p[m], off);

    float s2 = 0.f, d2 = 0.f;
#pragma unroll
    for (int m = 0; m < NCLS; m++) {
        s2 = fmaf(h2p[m], sas2[m], s2);
        d2 = fmaf(h2p[m], sad2[m], d2);
    }
    if (lane == 0) { g_as2[warp] = s2; g_ad2[warp] = d2; }

    float sel = h2p[0];
#pragma unroll
    for (int m = 1; m < NCLS; m++) sel = (lane == m) ? h2p[m] : sel;
    if (lane < NCLS) g_h2[warp * NCLS + lane] = sel;
}

// ---------------- layer-2 softmax aggregation ----------------
__global__ void agg2_k(const float* __restrict__ b2, float* __restrict__ out, int N) {
    int warp = (blockIdx.x * blockDim.x + threadIdx.x) >> 5;
    if (warp >= N) return;
    int lane = threadIdx.x & 31;
    int s = g_start[warp], e = g_start[warp + 1];
    float adv = g_ad2[warp];
    bool lo = (lane < NCLS);

    float acc = 0.f, den = 0.f;
    int i = s;
    for (; i + 1 < e; i += 2) {
        int2 ea = g_csr[i];
        int2 eb = g_csr[i + 1];
        float la = g_as2[ea.x] + adv;
        float lb = g_as2[eb.x] + adv;
        float fa = lo ? g_h2[(size_t)ea.x * NCLS + lane] : 0.f;
        float fb = lo ? g_h2[(size_t)eb.x * NCLS + lane] : 0.f;
        la = (la > 0.f ? la : 0.2f * la) * __int_as_float(ea.y);
        lb = (lb > 0.f ? lb : 0.2f * lb) * __int_as_float(eb.y);
        float xa = __expf(la), xb = __expf(lb);
        den += xa + xb;
        acc = fmaf(xa, fa, acc);
        acc = fmaf(xb, fb, acc);
    }
    if (i < e) {
        int2 ea = g_csr[i];
        float la = g_as2[ea.x] + adv;
        la = (la > 0.f ? la : 0.2f * la) * __int_as_float(ea.y);
        float xa = __expf(la);
        den += xa;
        if (lo) acc = fmaf(xa, g_h2[(size_t)ea.x * NCLS + lane], acc);
    }
    if (lo) out[(size_t)warp * NCLS + lane] = acc / (den + 1e-16f) + b2[lane];
}

// ---------------- launch ----------------
extern "C" void kernel_launch(void* const* d_in, const int* in_sizes, int n_in,
                              void* d_out, int out_size) {
    const float* x   = (const float*)d_in[0];
    const int*   ei  = (const int*)  d_in[1];
    const float* ew  = (const float*)d_in[2];
    const float* W1  = (const float*)d_in[3];
    const float* as1 = (const float*)d_in[4];
    const float* ad1 = (const float*)d_in[5];
    const float* b1  = (const float*)d_in[6];
    const float* W2  = (const float*)d_in[7];
    const float* as2 = (const float*)d_in[8];
    const float* ad2 = (const float*)d_in[9];
    const float* b2  = (const float*)d_in[10];
    float* out = (float*)d_out;

    int N  = in_sizes[0] / IN_CH;
    int E  = in_sizes[2];
    int ET = E + N;

    float *h1;
    void *degp, *xh, *xl, *wh, *wl;
    cudaGetSymbolAddress((void**)&h1, g_h1);
    cudaGetSymbolAddress(&degp, g_deg);
    cudaGetSymbolAddress(&xh, g_xh);
    cudaGetSymbolAddress(&xl, g_xl);
    cudaGetSymbolAddress(&wh, g_wh);
    cudaGetSymbolAddress(&wl, g_wl);

    // CSR build
    cudaMemsetAsync(degp, 0, (size_t)N * sizeof(int));
    hist_k<<<(ET + 255) / 256, 256>>>(ei, E, ET);
    scan_k<<<1, 1024>>>(N);
    scatter_k<<<(ET + 255) / 256, 256>>>(ei, ew, E, ET);

    // hi/lo split conversion
    int n4x = (N * IN_CH) / 4;
    conv_k<<<(n4x + 255) / 256, 256>>>((const float4*)x, (uint2*)xh, (uint2*)xl, n4x);
    int n4w = (IN_CH * HIDHEAD) / 4;
    conv_k<<<(n4w + 255) / 256, 256>>>((const float4*)W1, (uint2*)wh, (uint2*)wl, n4w);

    // layer 1 GEMM (tensor core) + att1 fused
    {
        dim3 grid((N + 127) / 128, 2);
        mma_gemm_att_k<<<grid, 256>>>((const __nv_bfloat16*)xh, (const __nv_bfloat16*)xl,
                                      (const __nv_bfloat16*)wh, (const __nv_bfloat16*)wl,
                                      h1, as1, ad1, N);
    }
    agg1_k<<<(N + 7) / 8, 256>>>(b1, W2, as2, ad2, N);

    // layer 2
    agg2_k<<<(N + 7) / 8, 256>>>(b2, out, N);
}

// round 6
// speedup vs baseline: 1.3702x; 1.0359x over previous
#include <cuda_runtime.h>
#include <cuda_bf16.h>
#include <math.h>
#include <stdint.h>

#define N_NODES 20000
#define N_EDGES 320000
#define IN_CH   256
#define HIDHEAD 256
#define HEADS   8
#define HID     32
#define NCLS    16
#define ET_MAX  (N_EDGES + N_NODES)

// ---------------- scratch ----------------
__device__ float g_h1  [(size_t)N_NODES * HIDHEAD];
__device__ float g_h2  [(size_t)N_NODES * NCLS];
__device__ float g_as1 [N_NODES * HEADS];
__device__ float g_ad1 [N_NODES * HEADS];
__device__ float g_as2 [N_NODES];
__device__ float g_ad2 [N_NODES];
__device__ int   g_deg [N_NODES];
__device__ int   g_start[N_NODES + 1];
__device__ int   g_cursor[N_NODES];
__device__ int2  g_csr [ET_MAX];

// ---------------- CSR build ----------------
__global__ void hist_k(const int* __restrict__ ei, int E, int ET) {
    int e = blockIdx.x * blockDim.x + threadIdx.x;
    if (e >= ET) return;
    int dst = (e < E) ? ei[E + e] : (e - E);
    atomicAdd(&g_deg[dst], 1);
}

__global__ void scan_k(int n) {
    __shared__ int sh[1024];
    int tid = threadIdx.x;
    int chunk = (n + 1023) / 1024;
    int b = tid * chunk;
    int e = b + chunk; if (e > n) e = n;
    int s = 0;
    for (int i = b; i < e; i++) s += g_deg[i];
    sh[tid] = s;
    __syncthreads();
    for (int off = 1; off < 1024; off <<= 1) {
        int t = (tid >= off) ? sh[tid - off] : 0;
        __syncthreads();
        sh[tid] += t;
        __syncthreads();
    }
    int run = sh[tid] - s;
    for (int i = b; i < e; i++) {
        g_start[i] = run;
        g_cursor[i] = run;
        run += g_deg[i];
    }
    if (tid == 1023) g_start[n] = sh[1023];
}

__global__ void scatter_k(const int* __restrict__ ei, const float* __restrict__ ew,
                          int E, int ET) {
    int e = blockIdx.x * blockDim.x + threadIdx.x;
    if (e >= ET) return;
    int src, dst; float w;
    if (e < E) { src = ei[e]; dst = ei[E + e]; w = ew[e]; }
    else       { src = e - E; dst = e - E;     w = 1.0f; }
    int pos = atomicAdd(&g_cursor[dst], 1);
    g_csr[pos] = make_int2(src, __float_as_int(w));
}

// ---------------- mma helpers ----------------
__device__ __forceinline__ void mma16816(float* c, const uint32_t* a, const uint32_t* b) {
    asm volatile("mma.sync.aligned.m16n8k16.row.col.f32.bf16.bf16.f32 "
        "{%0,%1,%2,%3}, {%4,%5,%6,%7}, {%8,%9}, {%0,%1,%2,%3};"
        : "+f"(c[0]), "+f"(c[1]), "+f"(c[2]), "+f"(c[3])
        : "r"(a[0]), "r"(a[1]), "r"(a[2]), "r"(a[3]), "r"(b[0]), "r"(b[1]));
}
__device__ __forceinline__ void ldsm4(uint32_t* r, uint32_t a) {
    asm volatile("ldmatrix.sync.aligned.m8n8.x4.shared.b16 {%0,%1,%2,%3}, [%4];"
        : "=r"(r[0]), "=r"(r[1]), "=r"(r[2]), "=r"(r[3]) : "r"(a));
}
__device__ __forceinline__ void ldsm4t(uint32_t* r, uint32_t a) {
    asm volatile("ldmatrix.sync.aligned.m8n8.x4.trans.shared.b16 {%0,%1,%2,%3}, [%4];"
        : "=r"(r[0]), "=r"(r[1]), "=r"(r[2]), "=r"(r[3]) : "r"(a));
}

// fp32x4 -> bf16 hi(uint2) + lo(uint2)
__device__ __forceinline__ void split4(float4 v, uint2& hi, uint2& lo) {
    __nv_bfloat162 h0 = __floats2bfloat162_rn(v.x, v.y);
    __nv_bfloat162 h1 = __floats2bfloat162_rn(v.z, v.w);
    __nv_bfloat162 l0 = __floats2bfloat162_rn(v.x - __low2float(h0), v.y - __high2float(h0));
    __nv_bfloat162 l1 = __floats2bfloat162_rn(v.z - __low2float(h1), v.w - __high2float(h1));
    hi.x = *reinterpret_cast<unsigned*>(&h0);
    hi.y = *reinterpret_cast<unsigned*>(&h1);
    lo.x = *reinterpret_cast<unsigned*>(&l0);
    lo.y = *reinterpret_cast<unsigned*>(&l1);
}

// ---------------- GEMM1 (in-register bf16 split, tensor core) + fused att1 ----------------
// C[N,256] = X[N,256] @ W[256,256]; block tile 128x256, 512 threads (16 warps, 4m x 4n),
// warp tile 32x64, k-step 16, double-buffered dynamic smem (57344 B):
//   A: stage*12288 + d*6144 + row*48 + byte           (rows padded to 48B)
//   B: 24576 + stage*16384 + d*8192 + k*512 + (c ^ (k&7))*16
__global__ __launch_bounds__(512)
void mma_gemm_att_k(const float* __restrict__ X, const float* __restrict__ W,
                    float* __restrict__ C,
                    const float* __restrict__ asw, const float* __restrict__ adw, int N) {
    extern __shared__ __align__(16) unsigned char smem[];
    const uint32_t sb = (uint32_t)__cvta_generic_to_shared(smem);

    int tid = threadIdx.x;
    int wid = tid >> 5, lane = tid & 31;
    int wm = wid & 3, wn = wid >> 2;
    int row0 = blockIdx.x * 128;

    float acc[2][8][4];
#pragma unroll
    for (int mi = 0; mi < 2; mi++)
#pragma unroll
        for (int ni = 0; ni < 8; ni++)
#pragma unroll
            for (int q = 0; q < 4; q++) acc[mi][ni][q] = 0.f;

    // ---- load assignments ----
    int atr = tid >> 2, atq = tid & 3;           // A: row, col-quad (4 fp32)
    int arow = row0 + atr;
    bool aok = (arow < N);
    const float4* Ag = (const float4*)(X + (size_t)(aok ? arow : 0) * 256);
    uint32_t sAa = (uint32_t)atr * 48 + (uint32_t)atq * 8;

    int btr = tid >> 5, btc = tid & 31;          // B: k-row, 8-col chunk
    const float4* Bg = (const float4*)W + (size_t)btr * 64 + btc * 2;
    uint32_t sBa = 24576u + (uint32_t)btr * 512 + (uint32_t)((btc ^ (btr & 7)) * 16);

    // ---- fragment addresses (stage-relative) ----
    uint32_t aoff[2][2];
#pragma unroll
    for (int dd = 0; dd < 2; dd++)
#pragma unroll
        for (int mi = 0; mi < 2; mi++)
            aoff[dd][mi] = (uint32_t)dd * 6144 +
                           (uint32_t)(wm * 32 + mi * 16 + (lane & 15)) * 48 +
                           (uint32_t)(lane >> 4) * 16;
    uint32_t boff[2][4];
#pragma unroll
    for (int dd = 0; dd < 2; dd++)
#pragma unroll
        for (int p = 0; p < 4; p++) {
            int kk = lane & 15;
            int cc = wn * 8 + p * 2 + (lane >> 4);
            boff[dd][p] = 24576u + (uint32_t)dd * 8192 + (uint32_t)kk * 512 +
                          (uint32_t)((cc ^ (kk & 7)) * 16);
        }

    // ---- preload + convert k-step 0 ----
    float4 av = aok ? Ag[atq] : make_float4(0.f, 0.f, 0.f, 0.f);
    float4 bv0 = Bg[0], bv1 = Bg[1];
    {
        uint2 ah_, al_; split4(av, ah_, al_);
        *(uint2*)(smem + sAa)        = ah_;
        *(uint2*)(smem + 6144 + sAa) = al_;
        uint2 bh0, bl0, bh1, bl1;
        split4(bv0, bh0, bl0); split4(bv1, bh1, bl1);
        *(uint4*)(smem + sBa)        = make_uint4(bh0.x, bh0.y, bh1.x, bh1.y);
        *(uint4*)(smem + 8192 + sBa) = make_uint4(bl0.x, bl0.y, bl1.x, bl1.y);
    }
    __syncthreads();

    uint32_t stA = 0, stB = 0;
    for (int kt = 0; kt < 16; kt++) {
        if (kt < 15) {
            av = aok ? Ag[(kt + 1) * 4 + atq] : make_float4(0.f, 0.f, 0.f, 0.f);
            bv0 = Bg[(size_t)(kt + 1) * 1024];
            bv1 = Bg[(size_t)(kt + 1) * 1024 + 1];
        }

        uint32_t ah[2][4], al[2][4];
#pragma unroll
        for (int mi = 0; mi < 2; mi++) {
            ldsm4(ah[mi], sb + stA + aoff[0][mi]);
            ldsm4(al[mi], sb + stA + aoff[1][mi]);
        }
#pragma unroll
        for (int p = 0; p < 4; p++) {
            uint32_t bh[4], bl[4];
            ldsm4t(bh, sb + stB + boff[0][p]);
            ldsm4t(bl, sb + stB + boff[1][p]);
#pragma unroll
            for (int mi = 0; mi < 2; mi++) {
                mma16816(acc[mi][p * 2],     ah[mi], bh);
                mma16816(acc[mi][p * 2],     ah[mi], bl);
                mma16816(acc[mi][p * 2],     al[mi], bh);
                mma16816(acc[mi][p * 2 + 1], ah[mi], bh + 2);
                mma16816(acc[mi][p * 2 + 1], ah[mi], bl + 2);
                mma16816(acc[mi][p * 2 + 1], al[mi], bh + 2);
            }
        }

        if (kt < 15) {
            uint32_t nstA = stA ^ 12288u, nstB = stB ^ 16384u;
            uint2 ah_, al_; split4(av, ah_, al_);
            *(uint2*)(smem + nstA + sAa)        = ah_;
            *(uint2*)(smem + nstA + 6144 + sAa) = al_;
            uint2 bh0, bl0, bh1, bl1;
            split4(bv0, bh0, bl0); split4(bv1, bh1, bl1);
            *(uint4*)(smem + nstB + sBa)        = make_uint4(bh0.x, bh0.y, bh1.x, bh1.y);
            *(uint4*)(smem + nstB + 8192 + sBa) = make_uint4(bl0.x, bl0.y, bl1.x, bl1.y);
            __syncthreads();
            stA = nstA; stB = nstB;
        }
    }

    // ---- store C ----
    int rbase = row0 + wm * 32 + (lane >> 2);
    int cbase = wn * 64 + (lane & 3) * 2;
#pragma unroll
    for (int mi = 0; mi < 2; mi++)
#pragma unroll
        for (int ni = 0; ni < 8; ni++) {
            int r = rbase + mi * 16;
            int c = cbase + ni * 8;
            if (r < N)
                *(float2*)(C + (size_t)r * 256 + c) = make_float2(acc[mi][ni][0], acc[mi][ni][1]);
            if (r + 8 < N)
                *(float2*)(C + (size_t)(r + 8) * 256 + c) = make_float2(acc[mi][ni][2], acc[mi][ni][3]);
        }

    // ---- fused att1 (warp covers heads wn*2, wn*2+1) ----
    int hg0 = wn * 2;
    float asr[2][8], adr[2][8];
#pragma unroll
    for (int h = 0; h < 2; h++)
#pragma unroll
        for (int q = 0; q < 4; q++) {
            int c = (hg0 + h) * 32 + q * 8 + (lane & 3) * 2;
            asr[h][q * 2]     = asw[c];
            asr[h][q * 2 + 1] = asw[c + 1];
            adr[h][q * 2]     = adw[c];
            adr[h][q * 2 + 1] = adw[c + 1];
        }
#pragma unroll
    for (int mi = 0; mi < 2; mi++)
#pragma unroll
        for (int half = 0; half < 2; half++) {
            float ps0 = 0.f, pd0 = 0.f, ps1 = 0.f, pd1 = 0.f;
#pragma unroll
            for (int q = 0; q < 4; q++) {
                float v0 = acc[mi][q][half * 2], v1 = acc[mi][q][half * 2 + 1];
                ps0 = fmaf(v0, asr[0][q * 2], ps0); ps0 = fmaf(v1, asr[0][q * 2 + 1], ps0);
                pd0 = fmaf(v0, adr[0][q * 2], pd0); pd0 = fmaf(v1, adr[0][q * 2 + 1], pd0);
                float u0 = acc[mi][4 + q][half * 2], u1 = acc[mi][4 + q][half * 2 + 1];
                ps1 = fmaf(u0, asr[1][q * 2], ps1); ps1 = fmaf(u1, asr[1][q * 2 + 1], ps1);
                pd1 = fmaf(u0, adr[1][q * 2], pd1); pd1 = fmaf(u1, adr[1][q * 2 + 1], pd1);
            }
            ps0 += __shfl_xor_sync(0xffffffffu, ps0, 1); ps0 += __shfl_xor_sync(0xffffffffu, ps0, 2);
            pd0 += __shfl_xor_sync(0xffffffffu, pd0, 1); pd0 += __shfl_xor_sync(0xffffffffu, pd0, 2);
            ps1 += __shfl_xor_sync(0xffffffffu, ps1, 1); ps1 += __shfl_xor_sync(0xffffffffu, ps1, 2);
            pd1 += __shfl_xor_sync(0xffffffffu, pd1, 1); pd1 += __shfl_xor_sync(0xffffffffu, pd1, 2);
            int r = row0 + wm * 32 + mi * 16 + half * 8 + (lane >> 2);
            if ((lane & 3) == 0 && r < N) {
                g_as1[r * HEADS + hg0]     = ps0;
                g_ad1[r * HEADS + hg0]     = pd0;
                g_as1[r * HEADS + hg0 + 1] = ps1;
                g_ad1[r * HEADS + hg0 + 1] = pd1;
            }
        }
}

// ---------------- layer-1 aggregation fused with GEMM2 + att2 ----------------
__global__ void agg1_k(const float* __restrict__ b1, const float* __restrict__ W2,
                       const float* __restrict__ as2w, const float* __restrict__ ad2w,
                       int N) {
    __shared__ float sW2t[NCLS * 256];
    __shared__ float sas2[NCLS], sad2[NCLS];
    int tid = threadIdx.x;
    for (int i = tid; i < 256 * NCLS; i += 256) {
        int c = i >> 4, m = i & 15;
        sW2t[m * 256 + c] = W2[i];
    }
    if (tid < NCLS) { sas2[tid] = as2w[tid]; sad2[tid] = ad2w[tid]; }
    __syncthreads();

    int warp = blockIdx.x * 8 + (tid >> 5);
    if (warp >= N) return;
    int lane = tid & 31;
    int s = g_start[warp], e = g_start[warp + 1];
    float adv = (lane < HEADS) ? g_ad1[warp * HEADS + lane] : 0.f;
    int h0 = lane >> 3;
    bool is_head = (lane < HEADS);

    float4 acc0 = make_float4(0.f, 0.f, 0.f, 0.f);
    float4 acc1 = make_float4(0.f, 0.f, 0.f, 0.f);
    float den = 0.f;

    int i = s;
    for (; i + 3 < e; i += 4) {
        int2 ee[4];
        float asv[4];
        float4 v0[4], v1[4];
#pragma unroll
        for (int u = 0; u < 4; u++) ee[u] = g_csr[i + u];
#pragma unroll
        for (int u = 0; u < 4; u++)
            asv[u] = is_head ? g_as1[ee[u].x * HEADS + lane] : 0.f;
#pragma unroll
        for (int u = 0; u < 4; u++) {
            const float4* hp = (const float4*)(g_h1 + (size_t)ee[u].x * HIDHEAD);
            v0[u] = hp[lane];
            v1[u] = hp[lane + 32];
        }
#pragma unroll
        for (int u = 0; u < 4; u++) {
            float t = 0.f;
            if (is_head) {
                float uu = asv[u] + adv;
                uu = (uu > 0.f ? uu : 0.2f * uu) * __int_as_float(ee[u].y);
                t = __expf(uu);
            }
            den += t;
            float w0 = __shfl_sync(0xffffffffu, t, h0);
            float w1 = __shfl_sync(0xffffffffu, t, 4 + h0);
            acc0.x = fmaf(w0, v0[u].x, acc0.x); acc0.y = fmaf(w0, v0[u].y, acc0.y);
            acc0.z = fmaf(w0, v0[u].z, acc0.z); acc0.w = fmaf(w0, v0[u].w, acc0.w);
            acc1.x = fmaf(w1, v1[u].x, acc1.x); acc1.y = fmaf(w1, v1[u].y, acc1.y);
            acc1.z = fmaf(w1, v1[u].z, acc1.z); acc1.w = fmaf(w1, v1[u].w, acc1.w);
        }
    }
    for (; i < e; i++) {
        int2 ea = g_csr[i];
        float t = 0.f;
        if (is_head) {
            float u = g_as1[ea.x * HEADS + lane] + adv;
            u = (u > 0.f ? u : 0.2f * u) * __int_as_float(ea.y);
            t = __expf(u);
        }
        den += t;
        const float4* hp = (const float4*)(g_h1 + (size_t)ea.x * HIDHEAD);
        float4 va0 = hp[lane], va1 = hp[lane + 32];
        float w0 = __shfl_sync(0xffffffffu, t, h0);
        float w1 = __shfl_sync(0xffffffffu, t, 4 + h0);
        acc0.x = fmaf(w0, va0.x, acc0.x); acc0.y = fmaf(w0, va0.y, acc0.y);
        acc0.z = fmaf(w0, va0.z, acc0.z); acc0.w = fmaf(w0, va0.w, acc0.w);
        acc1.x = fmaf(w1, va1.x, acc1.x); acc1.y = fmaf(w1, va1.y, acc1.y);
        acc1.z = fmaf(w1, va1.z, acc1.z); acc1.w = fmaf(w1, va1.w, acc1.w);
    }

    float d0 = __shfl_sync(0xffffffffu, den, h0);
    float d1 = __shfl_sync(0xffffffffu, den, 4 + h0);
    float inv0 = 1.f / (d0 + 1e-16f);
    float inv1 = 1.f / (d1 + 1e-16f);
    float4 bb0 = ((const float4*)b1)[lane];
    float4 bb1 = ((const float4*)b1)[lane + 32];
    float o[8];
    o[0] = acc0.x * inv0 + bb0.x;  o[1] = acc0.y * inv0 + bb0.y;
    o[2] = acc0.z * inv0 + bb0.z;  o[3] = acc0.w * inv0 + bb0.w;
    o[4] = acc1.x * inv1 + bb1.x;  o[5] = acc1.y * inv1 + bb1.y;
    o[6] = acc1.z * inv1 + bb1.z;  o[7] = acc1.w * inv1 + bb1.w;
#pragma unroll
    for (int j = 0; j < 8; j++) o[j] = (o[j] > 0.f) ? o[j] : (__expf(o[j]) - 1.f);

    float h2p[NCLS];
#pragma unroll
    for (int m = 0; m < NCLS; m++) {
        float4 wv0 = *(const float4*)&sW2t[m * 256 + lane * 4];
        float4 wv1 = *(const float4*)&sW2t[m * 256 + 128 + lane * 4];
        h2p[m] = o[0] * wv0.x + o[1] * wv0.y + o[2] * wv0.z + o[3] * wv0.w
               + o[4] * wv1.x + o[5] * wv1.y + o[6] * wv1.z + o[7] * wv1.w;
    }
#pragma unroll
    for (int off = 16; off >= 1; off >>= 1)
#pragma unroll
        for (int m = 0; m < NCLS; m++)
            h2p[m] += __shfl_xor_sync(0xffffffffu, h2p[m], off);

    float s2 = 0.f, d2 = 0.f;
#pragma unroll
    for (int m = 0; m < NCLS; m++) {
        s2 = fmaf(h2p[m], sas2[m], s2);
        d2 = fmaf(h2p[m], sad2[m], d2);
    }
    if (lane == 0) { g_as2[warp] = s2; g_ad2[warp] = d2; }

    float sel = h2p[0];
#pragma unroll
    for (int m = 1; m < NCLS; m++) sel = (lane == m) ? h2p[m] : sel;
    if (lane < NCLS) g_h2[warp * NCLS + lane] = sel;
}

// ---------------- layer-2 softmax aggregation ----------------
__global__ void agg2_k(const float* __restrict__ b2, float* __restrict__ out, int N) {
    int warp = (blockIdx.x * blockDim.x + threadIdx.x) >> 5;
    if (warp >= N) return;
    int lane = threadIdx.x & 31;
    int s = g_start[warp], e = g_start[warp + 1];
    float adv = g_ad2[warp];
    bool lo = (lane < NCLS);

    float acc = 0.f, den = 0.f;
    int i = s;
    for (; i + 3 < e; i += 4) {
        int2 ee[4];
        float lg[4], fv[4];
#pragma unroll
        for (int u = 0; u < 4; u++) ee[u] = g_csr[i + u];
#pragma unroll
        for (int u = 0; u < 4; u++) lg[u] = g_as2[ee[u].x] + adv;
#pragma unroll
        for (int u = 0; u < 4; u++)
            fv[u] = lo ? g_h2[(size_t)ee[u].x * NCLS + lane] : 0.f;
#pragma unroll
        for (int u = 0; u < 4; u++) {
            float t = (lg[u] > 0.f ? lg[u] : 0.2f * lg[u]) * __int_as_float(ee[u].y);
            float x = __expf(t);
            den += x;
            acc = fmaf(x, fv[u], acc);
        }
    }
    for (; i < e; i++) {
        int2 ea = g_csr[i];
        float la = g_as2[ea.x] + adv;
        la = (la > 0.f ? la : 0.2f * la) * __int_as_float(ea.y);
        float xa = __expf(la);
        den += xa;
        if (lo) acc = fmaf(xa, g_h2[(size_t)ea.x * NCLS + lane], acc);
    }
    if (lo) out[(size_t)warp * NCLS + lane] = acc / (den + 1e-16f) + b2[lane];
}

// ---------------- launch ----------------
extern "C" void kernel_launch(void* const* d_in, const int* in_sizes, int n_in,
                              void* d_out, int out_size) {
    const float* x   = (const float*)d_in[0];
    const int*   ei  = (const int*)  d_in[1];
    const float* ew  = (const float*)d_in[2];
    const float* W1  = (const float*)d_in[3];
    const float* as1 = (const float*)d_in[4];
    const float* ad1 = (const float*)d_in[5];
    const float* b1  = (const float*)d_in[6];
    const float* W2  = (const float*)d_in[7];
    const float* as2 = (const float*)d_in[8];
    const float* ad2 = (const float*)d_in[9];
    const float* b2  = (const float*)d_in[10];
    float* out = (float*)d_out;

    int N  = in_sizes[0] / IN_CH;
    int E  = in_sizes[2];
    int ET = E + N;

    float *h1;
    void *degp;
    cudaGetSymbolAddress((void**)&h1, g_h1);
    cudaGetSymbolAddress(&degp, g_deg);

    // CSR build
    cudaMemsetAsync(degp, 0, (size_t)N * sizeof(int));
    hist_k<<<(ET + 255) / 256, 256>>>(ei, E, ET);
    scan_k<<<1, 1024>>>(N);
    scatter_k<<<(ET + 255) / 256, 256>>>(ei, ew, E, ET);

    // layer 1 GEMM (tensor core, in-register bf16 split) + att1 fused
    {
        const int SMEM = 57344;
        cudaFuncSetAttribute(mma_gemm_att_k, cudaFuncAttributeMaxDynamicSharedMemorySize, SMEM);
        mma_gemm_att_k<<<(N + 127) / 128, 512, SMEM>>>(x, W1, h1, as1, ad1, N);
    }
    agg1_k<<<(N + 7) / 8, 256>>>(b1, W2, as2, ad2, N);

    // layer 2
    agg2_k<<<(N + 7) / 8, 256>>>(b2, out, N);
}

// round 7
// speedup vs baseline: 1.3832x; 1.0095x over previous
#include <cuda_runtime.h>
#include <cuda_bf16.h>
#include <math.h>
#include <stdint.h>

#define N_NODES 20000
#define N_EDGES 320000
#define IN_CH   256
#define HIDHEAD 256
#define HEADS   8
#define HID     32
#define NCLS    16
#define ET_MAX  (N_EDGES + N_NODES)

// ---------------- scratch ----------------
__device__ float g_h1  [(size_t)N_NODES * HIDHEAD];
__device__ float g_h2  [(size_t)N_NODES * NCLS];
__device__ float g_as1 [N_NODES * HEADS];
__device__ float g_ad1 [N_NODES * HEADS];
__device__ float g_as2 [N_NODES];
__device__ float g_ad2 [N_NODES];
__device__ int   g_deg [N_NODES];
__device__ int   g_start[N_NODES + 1];
__device__ int   g_cursor[N_NODES];
__device__ int2  g_csr [ET_MAX];
__device__ __nv_bfloat16 g_xh[(size_t)N_NODES * IN_CH];
__device__ __nv_bfloat16 g_xl[(size_t)N_NODES * IN_CH];
__device__ __nv_bfloat16 g_wh[IN_CH * HIDHEAD];
__device__ __nv_bfloat16 g_wl[IN_CH * HIDHEAD];

// ---------------- CSR build ----------------
__global__ void hist_k(const int* __restrict__ ei, int E, int ET) {
    int e = blockIdx.x * blockDim.x + threadIdx.x;
    if (e >= ET) return;
    int dst = (e < E) ? ei[E + e] : (e - E);
    atomicAdd(&g_deg[dst], 1);
}

__global__ void scan_k(int n) {
    __shared__ int sh[1024];
    int tid = threadIdx.x;
    int chunk = (n + 1023) / 1024;
    int b = tid * chunk;
    int e = b + chunk; if (e > n) e = n;
    int s = 0;
    for (int i = b; i < e; i++) s += g_deg[i];
    sh[tid] = s;
    __syncthreads();
    for (int off = 1; off < 1024; off <<= 1) {
        int t = (tid >= off) ? sh[tid - off] : 0;
        __syncthreads();
        sh[tid] += t;
        __syncthreads();
    }
    int run = sh[tid] - s;
    for (int i = b; i < e; i++) {
        g_start[i] = run;
        g_cursor[i] = run;
        run += g_deg[i];
    }
    if (tid == 1023) g_start[n] = sh[1023];
}

__global__ void scatter_k(const int* __restrict__ ei, const float* __restrict__ ew,
                          int E, int ET) {
    int e = blockIdx.x * blockDim.x + threadIdx.x;
    if (e >= ET) return;
    int src, dst; float w;
    if (e < E) { src = ei[e]; dst = ei[E + e]; w = ew[e]; }
    else       { src = e - E; dst = e - E;     w = 1.0f; }
    int pos = atomicAdd(&g_cursor[dst], 1);
    g_csr[pos] = make_int2(src, __float_as_int(w));
}

// ---------------- fp32 -> bf16 hi/lo split ----------------
__global__ void conv_k(const float4* __restrict__ src, uint2* __restrict__ hp,
                       uint2* __restrict__ lp, int n4) {
    int i = blockIdx.x * blockDim.x + threadIdx.x;
    if (i >= n4) return;
    float4 v = src[i];
    __nv_bfloat162 h0 = __floats2bfloat162_rn(v.x, v.y);
    __nv_bfloat162 h1 = __floats2bfloat162_rn(v.z, v.w);
    __nv_bfloat162 l0 = __floats2bfloat162_rn(v.x - __low2float(h0), v.y - __high2float(h0));
    __nv_bfloat162 l1 = __floats2bfloat162_rn(v.z - __low2float(h1), v.w - __high2float(h1));
    uint2 uh, ul;
    uh.x = *reinterpret_cast<unsigned*>(&h0);
    uh.y = *reinterpret_cast<unsigned*>(&h1);
    ul.x = *reinterpret_cast<unsigned*>(&l0);
    ul.y = *reinterpret_cast<unsigned*>(&l1);
    hp[i] = uh;
    lp[i] = ul;
}

// ---------------- mma / cp.async helpers ----------------
__device__ __forceinline__ void mma16816(float* c, const uint32_t* a, const uint32_t* b) {
    asm volatile("mma.sync.aligned.m16n8k16.row.col.f32.bf16.bf16.f32 "
        "{%0,%1,%2,%3}, {%4,%5,%6,%7}, {%8,%9}, {%0,%1,%2,%3};"
        : "+f"(c[0]), "+f"(c[1]), "+f"(c[2]), "+f"(c[3])
        : "r"(a[0]), "r"(a[1]), "r"(a[2]), "r"(a[3]), "r"(b[0]), "r"(b[1]));
}
__device__ __forceinline__ void ldsm4(uint32_t* r, uint32_t a) {
    asm volatile("ldmatrix.sync.aligned.m8n8.x4.shared.b16 {%0,%1,%2,%3}, [%4];"
        : "=r"(r[0]), "=r"(r[1]), "=r"(r[2]), "=r"(r[3]) : "r"(a));
}
__device__ __forceinline__ void ldsm4t(uint32_t* r, uint32_t a) {
    asm volatile("ldmatrix.sync.aligned.m8n8.x4.trans.shared.b16 {%0,%1,%2,%3}, [%4];"
        : "=r"(r[0]), "=r"(r[1]), "=r"(r[2]), "=r"(r[3]) : "r"(a));
}
__device__ __forceinline__ void cp16(uint32_t dst, const void* src) {
    asm volatile("cp.async.cg.shared.global [%0], [%1], 16;" :: "r"(dst), "l"(src));
}
__device__ __forceinline__ void cp_commit() {
    asm volatile("cp.async.commit_group;");
}
template <int NN>
__device__ __forceinline__ void cp_wait() {
    asm volatile("cp.async.wait_group %0;" :: "n"(NN));
}

// ---------------- GEMM1 (bf16 planes, cp.async 4-stage) + fused att1 ----------------
// C[N,256] = X @ W; block tile 128x256, 512 threads (16 warps, 4m x 4n), warp 32x64.
// smem per stage: A 12288 B (2 planes x 128 rows x 48B-stride) at stage*12288,
//                 B 16384 B (2 planes x 16k x 512B swizzled) at 49152 + stage*16384.
// Total dynamic smem = 49152 + 4*16384 = 114688.
#define STAGES 4
#define A_ST   12288u
#define B_BASE 49152u
#define B_ST   16384u
__global__ __launch_bounds__(512)
void mma_gemm_att_k(const __nv_bfloat16* __restrict__ Ah, const __nv_bfloat16* __restrict__ Al,
                    const __nv_bfloat16* __restrict__ Bh, const __nv_bfloat16* __restrict__ Bl,
                    float* __restrict__ C,
                    const float* __restrict__ asw, const float* __restrict__ adw, int N) {
    extern __shared__ __align__(16) unsigned char smem[];
    const uint32_t sb = (uint32_t)__cvta_generic_to_shared(smem);

    int tid = threadIdx.x;
    int wid = tid >> 5, lane = tid & 31;
    int wm = wid & 3, wn = wid >> 2;
    int row0 = blockIdx.x * 128;

    float acc[2][8][4];
#pragma unroll
    for (int mi = 0; mi < 2; mi++)
#pragma unroll
        for (int ni = 0; ni < 8; ni++)
#pragma unroll
            for (int q = 0; q < 4; q++) acc[mi][ni][q] = 0.f;

    // ---- cp.async load assignments ----
    // A: 512 chunks of 16B per stage: d = tid>>8, r = (tid&255)>>1, q = tid&1
    int ad_ = tid >> 8, ar_ = (tid & 255) >> 1, aq_ = tid & 1;
    int arow = row0 + ar_;
    bool aok = (arow < N);
    const __nv_bfloat16* Asrc = (ad_ ? Al : Ah) + (size_t)(aok ? arow : 0) * 256 + aq_ * 8;
    uint32_t sAdst = sb + (uint32_t)ad_ * 6144 + (uint32_t)ar_ * 48 + (uint32_t)aq_ * 16;
    // B: 1024 chunks per stage, 2 per thread (l=0 -> hi, l=1 -> lo)
    int bj = tid & 511;
    int bk_ = bj >> 5, bc_ = bj & 31;
    const __nv_bfloat16* Bsrc0 = Bh + (size_t)bk_ * 256 + bc_ * 8;
    const __nv_bfloat16* Bsrc1 = Bl + (size_t)bk_ * 256 + bc_ * 8;
    uint32_t sBdst = sb + B_BASE + (uint32_t)bk_ * 512 + (uint32_t)((bc_ ^ (bk_ & 7)) * 16);

    // ---- fragment addresses (stage-relative) ----
    uint32_t aoff[2][2];
#pragma unroll
    for (int dd = 0; dd < 2; dd++)
#pragma unroll
        for (int mi = 0; mi < 2; mi++)
            aoff[dd][mi] = sb + (uint32_t)dd * 6144 +
                           (uint32_t)(wm * 32 + mi * 16 + (lane & 15)) * 48 +
                           (uint32_t)(lane >> 4) * 16;
    uint32_t boff[2][4];
#pragma unroll
    for (int dd = 0; dd < 2; dd++)
#pragma unroll
        for (int p = 0; p < 4; p++) {
            int kk = lane & 15;
            int cc = wn * 8 + p * 2 + (lane >> 4);
            boff[dd][p] = sb + B_BASE + (uint32_t)dd * 8192 + (uint32_t)kk * 512 +
                          (uint32_t)((cc ^ (kk & 7)) * 16);
        }

    // ---- prologue: fill stages 0..2 ----
#pragma unroll
    for (int s = 0; s < STAGES - 1; s++) {
        if (aok) cp16(sAdst + s * A_ST, Asrc + s * 16);
        else {   // still issue to keep group counts uniform; copy row 0 (harmless, masked at use)
            cp16(sAdst + s * A_ST, Asrc + s * 16);
        }
        cp16(sBdst + s * B_ST,        Bsrc0 + (size_t)s * 16 * 256);
        cp16(sBdst + s * B_ST + 8192, Bsrc1 + (size_t)s * 16 * 256);
        cp_commit();
    }

    for (int kt = 0; kt < 16; kt++) {
        cp_wait<STAGES - 2>();
        __syncthreads();

        // issue stage kt+3
        if (kt + STAGES - 1 < 16) {
            int s = (kt + STAGES - 1) & (STAGES - 1);
            cp16(sAdst + s * A_ST, Asrc + (kt + STAGES - 1) * 16);
            cp16(sBdst + s * B_ST,        Bsrc0 + (size_t)(kt + STAGES - 1) * 16 * 256);
            cp16(sBdst + s * B_ST + 8192, Bsrc1 + (size_t)(kt + STAGES - 1) * 16 * 256);
        }
        cp_commit();

        uint32_t stA = (uint32_t)(kt & (STAGES - 1)) * A_ST;
        uint32_t stB = (uint32_t)(kt & (STAGES - 1)) * B_ST;

        uint32_t ah[2][4], al[2][4];
#pragma unroll
        for (int mi = 0; mi < 2; mi++) {
            ldsm4(ah[mi], stA + aoff[0][mi]);
            ldsm4(al[mi], stA + aoff[1][mi]);
        }
#pragma unroll
        for (int p = 0; p < 4; p++) {
            uint32_t bh[4], bl[4];
            ldsm4t(bh, stB + boff[0][p]);
            ldsm4t(bl, stB + boff[1][p]);
#pragma unroll
            for (int mi = 0; mi < 2; mi++) {
                mma16816(acc[mi][p * 2],     ah[mi], bh);
                mma16816(acc[mi][p * 2],     ah[mi], bl);
                mma16816(acc[mi][p * 2],     al[mi], bh);
                mma16816(acc[mi][p * 2 + 1], ah[mi], bh + 2);
                mma16816(acc[mi][p * 2 + 1], ah[mi], bl + 2);
                mma16816(acc[mi][p * 2 + 1], al[mi], bh + 2);
            }
        }
        __syncthreads();   // all warps done with stage kt before it is refilled
    }

    // ---- store C ----
    int rbase = row0 + wm * 32 + (lane >> 2);
    int cbase = wn * 64 + (lane & 3) * 2;
#pragma unroll
    for (int mi = 0; mi < 2; mi++)
#pragma unroll
        for (int ni = 0; ni < 8; ni++) {
            int r = rbase + mi * 16;
            int c = cbase + ni * 8;
            if (r < N)
                *(float2*)(C + (size_t)r * 256 + c) = make_float2(acc[mi][ni][0], acc[mi][ni][1]);
            if (r + 8 < N)
                *(float2*)(C + (size_t)(r + 8) * 256 + c) = make_float2(acc[mi][ni][2], acc[mi][ni][3]);
        }

    // ---- fused att1 (warp covers heads wn*2, wn*2+1) ----
    int hg0 = wn * 2;
    float asr[2][8], adr[2][8];
#pragma unroll
    for (int h = 0; h < 2; h++)
#pragma unroll
        for (int q = 0; q < 4; q++) {
            int c = (hg0 + h) * 32 + q * 8 + (lane & 3) * 2;
            asr[h][q * 2]     = asw[c];
            asr[h][q * 2 + 1] = asw[c + 1];
            adr[h][q * 2]     = adw[c];
            adr[h][q * 2 + 1] = adw[c + 1];
        }
#pragma unroll
    for (int mi = 0; mi < 2; mi++)
#pragma unroll
        for (int half = 0; half < 2; half++) {
            float ps0 = 0.f, pd0 = 0.f, ps1 = 0.f, pd1 = 0.f;
#pragma unroll
            for (int q = 0; q < 4; q++) {
                float v0 = acc[mi][q][half * 2], v1 = acc[mi][q][half * 2 + 1];
                ps0 = fmaf(v0, asr[0][q * 2], ps0); ps0 = fmaf(v1, asr[0][q * 2 + 1], ps0);
                pd0 = fmaf(v0, adr[0][q * 2], pd0); pd0 = fmaf(v1, adr[0][q * 2 + 1], pd0);
                float u0 = acc[mi][4 + q][half * 2], u1 = acc[mi][4 + q][half * 2 + 1];
                ps1 = fmaf(u0, asr[1][q * 2], ps1); ps1 = fmaf(u1, asr[1][q * 2 + 1], ps1);
                pd1 = fmaf(u0, adr[1][q * 2], pd1); pd1 = fmaf(u1, adr[1][q * 2 + 1], pd1);
            }
            ps0 += __shfl_xor_sync(0xffffffffu, ps0, 1); ps0 += __shfl_xor_sync(0xffffffffu, ps0, 2);
            pd0 += __shfl_xor_sync(0xffffffffu, pd0, 1); pd0 += __shfl_xor_sync(0xffffffffu, pd0, 2);
            ps1 += __shfl_xor_sync(0xffffffffu, ps1, 1); ps1 += __shfl_xor_sync(0xffffffffu, ps1, 2);
            pd1 += __shfl_xor_sync(0xffffffffu, pd1, 1); pd1 += __shfl_xor_sync(0xffffffffu, pd1, 2);
            int r = row0 + wm * 32 + mi * 16 + half * 8 + (lane >> 2);
            if ((lane & 3) == 0 && r < N) {
                g_as1[r * HEADS + hg0]     = ps0;
                g_ad1[r * HEADS + hg0]     = pd0;
                g_as1[r * HEADS + hg0 + 1] = ps1;
                g_ad1[r * HEADS + hg0 + 1] = pd1;
            }
        }
}

// ---------------- layer-1 aggregation fused with GEMM2 + att2 ----------------
__global__ void agg1_k(const float* __restrict__ b1, const float* __restrict__ W2,
                       const float* __restrict__ as2w, const float* __restrict__ ad2w,
                       int N) {
    __shared__ float sW2t[NCLS * 256];
    __shared__ float sas2[NCLS], sad2[NCLS];
    int tid = threadIdx.x;
    for (int i = tid; i < 256 * NCLS; i += 256) {
        int c = i >> 4, m = i & 15;
        sW2t[m * 256 + c] = W2[i];
    }
    if (tid < NCLS) { sas2[tid] = as2w[tid]; sad2[tid] = ad2w[tid]; }
    __syncthreads();

    int warp = blockIdx.x * 8 + (tid >> 5);
    if (warp >= N) return;
    int lane = tid & 31;
    int s = g_start[warp], e = g_start[warp + 1];
    float adv = (lane < HEADS) ? g_ad1[warp * HEADS + lane] : 0.f;
    int h0 = lane >> 3;
    bool is_head = (lane < HEADS);

    float4 acc0 = make_float4(0.f, 0.f, 0.f, 0.f);
    float4 acc1 = make_float4(0.f, 0.f, 0.f, 0.f);
    float den = 0.f;

    int i = s;
    for (; i + 3 < e; i += 4) {
        int2 ee[4];
        float asv[4];
        float4 v0[4], v1[4];
#pragma unroll
        for (int u = 0; u < 4; u++) ee[u] = g_csr[i + u];
#pragma unroll
        for (int u = 0; u < 4; u++)
            asv[u] = is_head ? g_as1[ee[u].x * HEADS + lane] : 0.f;
#pragma unroll
        for (int u = 0; u < 4; u++) {
            const float4* hp = (const float4*)(g_h1 + (size_t)ee[u].x * HIDHEAD);
            v0[u] = hp[lane];
            v1[u] = hp[lane + 32];
        }
#pragma unroll
        for (int u = 0; u < 4; u++) {
            float t = 0.f;
            if (is_head) {
                float uu = asv[u] + adv;
                uu = (uu > 0.f ? uu : 0.2f * uu) * __int_as_float(ee[u].y);
                t = __expf(uu);
            }
            den += t;
            float w0 = __shfl_sync(0xffffffffu, t, h0);
            float w1 = __shfl_sync(0xffffffffu, t, 4 + h0);
            acc0.x = fmaf(w0, v0[u].x, acc0.x); acc0.y = fmaf(w0, v0[u].y, acc0.y);
            acc0.z = fmaf(w0, v0[u].z, acc0.z); acc0.w = fmaf(w0, v0[u].w, acc0.w);
            acc1.x = fmaf(w1, v1[u].x, acc1.x); acc1.y = fmaf(w1, v1[u].y, acc1.y);
            acc1.z = fmaf(w1, v1[u].z, acc1.z); acc1.w = fmaf(w1, v1[u].w, acc1.w);
        }
    }
    for (; i < e; i++) {
        int2 ea = g_csr[i];
        float t = 0.f;
        if (is_head) {
            float u = g_as1[ea.x * HEADS + lane] + adv;
            u = (u > 0.f ? u : 0.2f * u) * __int_as_float(ea.y);
            t = __expf(u);
        }
        den += t;
        const float4* hp = (const float4*)(g_h1 + (size_t)ea.x * HIDHEAD);
        float4 va0 = hp[lane], va1 = hp[lane + 32];
        float w0 = __shfl_sync(0xffffffffu, t, h0);
        float w1 = __shfl_sync(0xffffffffu, t, 4 + h0);
        acc0.x = fmaf(w0, va0.x, acc0.x); acc0.y = fmaf(w0, va0.y, acc0.y);
        acc0.z = fmaf(w0, va0.z, acc0.z); acc0.w = fmaf(w0, va0.w, acc0.w);
        acc1.x = fmaf(w1, va1.x, acc1.x); acc1.y = fmaf(w1, va1.y, acc1.y);
        acc1.z = fmaf(w1, va1.z, acc1.z); acc1.w = fmaf(w1, va1.w, acc1.w);
    }

    float d0 = __shfl_sync(0xffffffffu, den, h0);
    float d1 = __shfl_sync(0xffffffffu, den, 4 + h0);
    float inv0 = 1.f / (d0 + 1e-16f);
    float inv1 = 1.f / (d1 + 1e-16f);
    float4 bb0 = ((const float4*)b1)[lane];
    float4 bb1 = ((const float4*)b1)[lane + 32];
    float o[8];
    o[0] = acc0.x * inv0 + bb0.x;  o[1] = acc0.y * inv0 + bb0.y;
    o[2] = acc0.z * inv0 + bb0.z;  o[3] = acc0.w * inv0 + bb0.w;
    o[4] = acc1.x * inv1 + bb1.x;  o[5] = acc1.y * inv1 + bb1.y;
    o[6] = acc1.z * inv1 + bb1.z;  o[7] = acc1.w * inv1 + bb1.w;
#pragma unroll
    for (int j = 0; j < 8; j++) o[j] = (o[j] > 0.f) ? o[j] : (__expf(o[j]) - 1.f);

    float h2p[NCLS];
#pragma unroll
    for (int m = 0; m < NCLS; m++) {
        float4 wv0 = *(const float4*)&sW2t[m * 256 + lane * 4];
        float4 wv1 = *(const float4*)&sW2t[m * 256 + 128 + lane * 4];
        h2p[m] = o[0] * wv0.x + o[1] * wv0.y + o[2] * wv0.z + o[3] * wv0.w
               + o[4] * wv1.x + o[5] * wv1.y + o[6] * wv1.z + o[7] * wv1.w;
    }
#pragma unroll
    for (int off = 16; off >= 1; off >>= 1)
#pragma unroll
        for (int m = 0; m < NCLS; m++)
            h2p[m] += __shfl_xor_sync(0xffffffffu, h2p[m], off);

    float s2 = 0.f, d2 = 0.f;
#pragma unroll
    for (int m = 0; m < NCLS; m++) {
        s2 = fmaf(h2p[m], sas2[m], s2);
        d2 = fmaf(h2p[m], sad2[m], d2);
    }
    if (lane == 0) { g_as2[warp] = s2; g_ad2[warp] = d2; }

    float sel = h2p[0];
#pragma unroll
    for (int m = 1; m < NCLS; m++) sel = (lane == m) ? h2p[m] : sel;
    if (lane < NCLS) g_h2[warp * NCLS + lane] = sel;
}

// ---------------- layer-2 softmax aggregation ----------------
__global__ void agg2_k(const float* __restrict__ b2, float* __restrict__ out, int N) {
    int warp = (blockIdx.x * blockDim.x + threadIdx.x) >> 5;
    if (warp >= N) return;
    int lane = threadIdx.x & 31;
    int s = g_start[warp], e = g_start[warp + 1];
    float adv = g_ad2[warp];
    bool lo = (lane < NCLS);

    float acc = 0.f, den = 0.f;
    int i = s;
    for (; i + 3 < e; i += 4) {
        int2 ee[4];
        float lg[4], fv[4];
#pragma unroll
        for (int u = 0; u < 4; u++) ee[u] = g_csr[i + u];
#pragma unroll
        for (int u = 0; u < 4; u++) lg[u] = g_as2[ee[u].x] + adv;
#pragma unroll
        for (int u = 0; u < 4; u++)
            fv[u] = lo ? g_h2[(size_t)ee[u].x * NCLS + lane] : 0.f;
#pragma unroll
        for (int u = 0; u < 4; u++) {
            float t = (lg[u] > 0.f ? lg[u] : 0.2f * lg[u]) * __int_as_float(ee[u].y);
            float x = __expf(t);
            den += x;
            acc = fmaf(x, fv[u], acc);
        }
    }
    for (; i < e; i++) {
        int2 ea = g_csr[i];
        float la = g_as2[ea.x] + adv;
        la = (la > 0.f ? la : 0.2f * la) * __int_as_float(ea.y);
        float xa = __expf(la);
        den += xa;
        if (lo) acc = fmaf(xa, g_h2[(size_t)ea.x * NCLS + lane], acc);
    }
    if (lo) out[(size_t)warp * NCLS + lane] = acc / (den + 1e-16f) + b2[lane];
}

// ---------------- launch ----------------
extern "C" void kernel_launch(void* const* d_in, const int* in_sizes, int n_in,
                              void* d_out, int out_size) {
    const float* x   = (const float*)d_in[0];
    const int*   ei  = (const int*)  d_in[1];
    const float* ew  = (const float*)d_in[2];
    const float* W1  = (const float*)d_in[3];
    const float* as1 = (const float*)d_in[4];
    const float* ad1 = (const float*)d_in[5];
    const float* b1  = (const float*)d_in[6];
    const float* W2  = (const float*)d_in[7];
    const float* as2 = (const float*)d_in[8];
    const float* ad2 = (const float*)d_in[9];
    const float* b2  = (const float*)d_in[10];
    float* out = (float*)d_out;

    int N  = in_sizes[0] / IN_CH;
    int E  = in_sizes[2];
    int ET = E + N;

    float *h1;
    void *degp, *xh, *xl, *wh, *wl;
    cudaGetSymbolAddress((void**)&h1, g_h1);
    cudaGetSymbolAddress(&degp, g_deg);
    cudaGetSymbolAddress(&xh, g_xh);
    cudaGetSymbolAddress(&xl, g_xl);
    cudaGetSymbolAddress(&wh, g_wh);
    cudaGetSymbolAddress(&wl, g_wl);

    // hi/lo split conversion (issued first so it overlaps nothing heavy)
    int n4w = (IN_CH * HIDHEAD) / 4;
    conv_k<<<(n4w + 255) / 256, 256>>>((const float4*)W1, (uint2*)wh, (uint2*)wl, n4w);
    int n4x = (N * IN_CH) / 4;
    conv_k<<<(n4x + 255) / 256, 256>>>((const float4*)x, (uint2*)xh, (uint2*)xl, n4x);

    // CSR build
    cudaMemsetAsync(degp, 0, (size_t)N * sizeof(int));
    hist_k<<<(ET + 255) / 256, 256>>>(ei, E, ET);
    scan_k<<<1, 1024>>>(N);
    scatter_k<<<(ET + 255) / 256, 256>>>(ei, ew, E, ET);

    // layer 1 GEMM (tensor core, cp.async 4-stage) + att1 fused
    {
        const int SMEM = 114688;
        cudaFuncSetAttribute(mma_gemm_att_k, cudaFuncAttributeMaxDynamicSharedMemorySize, SMEM);
        mma_gemm_att_k<<<(N + 127) / 128, 512, SMEM>>>(
            (const __nv_bfloat16*)xh, (const __nv_bfloat16*)xl,
            (const __nv_bfloat16*)wh, (const __nv_bfloat16*)wl,
            h1, as1, ad1, N);
    }
    agg1_k<<<(N + 7) / 8, 256>>>(b1, W2, as2, ad2, N);

    // layer 2
    agg2_k<<<(N + 7) / 8, 256>>>(b2, out, N);
}

// round 8
// speedup vs baseline: 1.5750x; 1.1387x over previous
#include <cuda_runtime.h>
#include <cuda_bf16.h>
#include <math.h>
#include <stdint.h>

#define N_NODES 20000
#define N_EDGES 320000
#define IN_CH   256
#define HIDHEAD 256
#define HEADS   8
#define HID     32
#define NCLS    16
#define ET_MAX  (N_EDGES + N_NODES)
#define SCAN_B  512
#define NBLK    ((N_NODES + SCAN_B - 1) / SCAN_B)   // 40

// ---------------- scratch ----------------
__device__ float g_h1  [(size_t)N_NODES * HIDHEAD];
__device__ float g_h2  [(size_t)N_NODES * NCLS];
__device__ float g_as1 [N_NODES * HEADS];
__device__ float g_ad1 [N_NODES * HEADS];
__device__ float g_as2 [N_NODES];
__device__ float g_ad2 [N_NODES];
__device__ int   g_deg [N_NODES];
__device__ int   g_start[N_NODES + 1];
__device__ int   g_cursor[N_NODES];
__device__ int   g_bsum[NBLK];
__device__ int   g_boff[NBLK];
__device__ int2  g_csr [ET_MAX];
__device__ __nv_bfloat16 g_xh[(size_t)N_NODES * IN_CH];
__device__ __nv_bfloat16 g_xl[(size_t)N_NODES * IN_CH];
__device__ __nv_bfloat16 g_wh[IN_CH * HIDHEAD];
__device__ __nv_bfloat16 g_wl[IN_CH * HIDHEAD];

// ---------------- CSR build ----------------
__global__ void hist_k(const int* __restrict__ ei, int E, int ET) {
    int e = blockIdx.x * blockDim.x + threadIdx.x;
    if (e >= ET) return;
    int dst = (e < E) ? ei[E + e] : (e - E);
    atomicAdd(&g_deg[dst], 1);
}

// phase A: per-block exclusive scan of deg -> g_start (local), block total -> g_bsum
__global__ void scanA_k(int n) {
    __shared__ int sh[SCAN_B];
    int tid = threadIdx.x;
    int i = blockIdx.x * SCAN_B + tid;
    int v = (i < n) ? g_deg[i] : 0;
    sh[tid] = v;
    __syncthreads();
#pragma unroll
    for (int off = 1; off < SCAN_B; off <<= 1) {
        int t = (tid >= off) ? sh[tid - off] : 0;
        __syncthreads();
        sh[tid] += t;
        __syncthreads();
    }
    if (i < n) g_start[i] = sh[tid] - v;          // exclusive, local
    if (tid == SCAN_B - 1) g_bsum[blockIdx.x] = sh[tid];
}

// phase B: exclusive scan of the NBLK block sums; also write grand total to g_start[n]
__global__ void scanB_k(int n) {
    __shared__ int sh[64];
    int tid = threadIdx.x;                         // 64 threads
    int v = (tid < NBLK) ? g_bsum[tid] : 0;
    sh[tid] = v;
    __syncthreads();
#pragma unroll
    for (int off = 1; off < 64; off <<= 1) {
        int t = (tid >= off) ? sh[tid - off] : 0;
        __syncthreads();
        sh[tid] += t;
        __syncthreads();
    }
    if (tid < NBLK) g_boff[tid] = sh[tid] - v;     // exclusive
    if (tid == 63) g_start[n] = sh[63];            // grand total
}

// phase C: add block offset, materialize cursor
__global__ void scanC_k(int n) {
    int i = blockIdx.x * SCAN_B + threadIdx.x;
    if (i >= n) return;
    int s = g_start[i] + g_boff[blockIdx.x];
    g_start[i] = s;
    g_cursor[i] = s;
}

__global__ void scatter_k(const int* __restrict__ ei, const float* __restrict__ ew,
                          int E, int ET) {
    int e = blockIdx.x * blockDim.x + threadIdx.x;
    if (e >= ET) return;
    int src, dst; float w;
    if (e < E) { src = ei[e]; dst = ei[E + e]; w = ew[e]; }
    else       { src = e - E; dst = e - E;     w = 1.0f; }
    int pos = atomicAdd(&g_cursor[dst], 1);
    g_csr[pos] = make_int2(src, __float_as_int(w));
}

// ---------------- fp32 -> bf16 hi/lo split ----------------
__global__ void conv_k(const float4* __restrict__ src, uint2* __restrict__ hp,
                       uint2* __restrict__ lp, int n4) {
    int i = blockIdx.x * blockDim.x + threadIdx.x;
    if (i >= n4) return;
    float4 v = src[i];
    __nv_bfloat162 h0 = __floats2bfloat162_rn(v.x, v.y);
    __nv_bfloat162 h1 = __floats2bfloat162_rn(v.z, v.w);
    __nv_bfloat162 l0 = __floats2bfloat162_rn(v.x - __low2float(h0), v.y - __high2float(h0));
    __nv_bfloat162 l1 = __floats2bfloat162_rn(v.z - __low2float(h1), v.w - __high2float(h1));
    uint2 uh, ul;
    uh.x = *reinterpret_cast<unsigned*>(&h0);
    uh.y = *reinterpret_cast<unsigned*>(&h1);
    ul.x = *reinterpret_cast<unsigned*>(&l0);
    ul.y = *reinterpret_cast<unsigned*>(&l1);
    hp[i] = uh;
    lp[i] = ul;
}

// ---------------- mma / cp.async helpers ----------------
__device__ __forceinline__ void mma16816(float* c, const uint32_t* a, const uint32_t* b) {
    asm volatile("mma.sync.aligned.m16n8k16.row.col.f32.bf16.bf16.f32 "
        "{%0,%1,%2,%3}, {%4,%5,%6,%7}, {%8,%9}, {%0,%1,%2,%3};"
        : "+f"(c[0]), "+f"(c[1]), "+f"(c[2]), "+f"(c[3])
        : "r"(a[0]), "r"(a[1]), "r"(a[2]), "r"(a[3]), "r"(b[0]), "r"(b[1]));
}
__device__ __forceinline__ void ldsm4(uint32_t* r, uint32_t a) {
    asm volatile("ldmatrix.sync.aligned.m8n8.x4.shared.b16 {%0,%1,%2,%3}, [%4];"
        : "=r"(r[0]), "=r"(r[1]), "=r"(r[2]), "=r"(r[3]) : "r"(a));
}
__device__ __forceinline__ void ldsm4t(uint32_t* r, uint32_t a) {
    asm volatile("ldmatrix.sync.aligned.m8n8.x4.trans.shared.b16 {%0,%1,%2,%3}, [%4];"
        : "=r"(r[0]), "=r"(r[1]), "=r"(r[2]), "=r"(r[3]) : "r"(a));
}
__device__ __forceinline__ void cp16(uint32_t dst, const void* src) {
    asm volatile("cp.async.cg.shared.global [%0], [%1], 16;" :: "r"(dst), "l"(src));
}
__device__ __forceinline__ void cp_commit() {
    asm volatile("cp.async.commit_group;");
}
template <int NN>
__device__ __forceinline__ void cp_wait() {
    asm volatile("cp.async.wait_group %0;" :: "n"(NN));
}

// ---------------- GEMM1 (bf16 planes, cp.async 4-stage) + fused att1 ----------------
#define STAGES 4
#define A_ST   12288u
#define B_BASE 49152u
#define B_ST   16384u
__global__ __launch_bounds__(512)
void mma_gemm_att_k(const __nv_bfloat16* __restrict__ Ah, const __nv_bfloat16* __restrict__ Al,
                    const __nv_bfloat16* __restrict__ Bh, const __nv_bfloat16* __restrict__ Bl,
                    float* __restrict__ C,
                    const float* __restrict__ asw, const float* __restrict__ adw, int N) {
    extern __shared__ __align__(16) unsigned char smem[];
    const uint32_t sb = (uint32_t)__cvta_generic_to_shared(smem);

    int tid = threadIdx.x;
    int wid = tid >> 5, lane = tid & 31;
    int wm = wid & 3, wn = wid >> 2;
    int row0 = blockIdx.x * 128;

    float acc[2][8][4];
#pragma unroll
    for (int mi = 0; mi < 2; mi++)
#pragma unroll
        for (int ni = 0; ni < 8; ni++)
#pragma unroll
            for (int q = 0; q < 4; q++) acc[mi][ni][q] = 0.f;

    int ad_ = tid >> 8, ar_ = (tid & 255) >> 1, aq_ = tid & 1;
    int arow = row0 + ar_;
    bool aok = (arow < N);
    const __nv_bfloat16* Asrc = (ad_ ? Al : Ah) + (size_t)(aok ? arow : 0) * 256 + aq_ * 8;
    uint32_t sAdst = sb + (uint32_t)ad_ * 6144 + (uint32_t)ar_ * 48 + (uint32_t)aq_ * 16;
    int bj = tid & 511;
    int bk_ = bj >> 5, bc_ = bj & 31;
    const __nv_bfloat16* Bsrc0 = Bh + (size_t)bk_ * 256 + bc_ * 8;
    const __nv_bfloat16* Bsrc1 = Bl + (size_t)bk_ * 256 + bc_ * 8;
    uint32_t sBdst = sb + B_BASE + (uint32_t)bk_ * 512 + (uint32_t)((bc_ ^ (bk_ & 7)) * 16);

    uint32_t aoff[2][2];
#pragma unroll
    for (int dd = 0; dd < 2; dd++)
#pragma unroll
        for (int mi = 0; mi < 2; mi++)
            aoff[dd][mi] = sb + (uint32_t)dd * 6144 +
                           (uint32_t)(wm * 32 + mi * 16 + (lane & 15)) * 48 +
                           (uint32_t)(lane >> 4) * 16;
    uint32_t boff[2][4];
#pragma unroll
    for (int dd = 0; dd < 2; dd++)
#pragma unroll
        for (int p = 0; p < 4; p++) {
            int kk = lane & 15;
            int cc = wn * 8 + p * 2 + (lane >> 4);
            boff[dd][p] = sb + B_BASE + (uint32_t)dd * 8192 + (uint32_t)kk * 512 +
                          (uint32_t)((cc ^ (kk & 7)) * 16);
        }

#pragma unroll
    for (int s = 0; s < STAGES - 1; s++) {
        cp16(sAdst + s * A_ST, Asrc + s * 16);
        cp16(sBdst + s * B_ST,        Bsrc0 + (size_t)s * 16 * 256);
        cp16(sBdst + s * B_ST + 8192, Bsrc1 + (size_t)s * 16 * 256);
        cp_commit();
    }

    for (int kt = 0; kt < 16; kt++) {
        cp_wait<STAGES - 2>();
        __syncthreads();

        if (kt + STAGES - 1 < 16) {
            int s = (kt + STAGES - 1) & (STAGES - 1);
            cp16(sAdst + s * A_ST, Asrc + (kt + STAGES - 1) * 16);
            cp16(sBdst + s * B_ST,        Bsrc0 + (size_t)(kt + STAGES - 1) * 16 * 256);
            cp16(sBdst + s * B_ST + 8192, Bsrc1 + (size_t)(kt + STAGES - 1) * 16 * 256);
        }
        cp_commit();

        uint32_t stA = (uint32_t)(kt & (STAGES - 1)) * A_ST;
        uint32_t stB = (uint32_t)(kt & (STAGES - 1)) * B_ST;

        uint32_t ah[2][4], al[2][4];
#pragma unroll
        for (int mi = 0; mi < 2; mi++) {
            ldsm4(ah[mi], stA + aoff[0][mi]);
            ldsm4(al[mi], stA + aoff[1][mi]);
        }
#pragma unroll
        for (int p = 0; p < 4; p++) {
            uint32_t bh[4], bl[4];
            ldsm4t(bh, stB + boff[0][p]);
            ldsm4t(bl, stB + boff[1][p]);
#pragma unroll
            for (int mi = 0; mi < 2; mi++) {
                mma16816(acc[mi][p * 2],     ah[mi], bh);
                mma16816(acc[mi][p * 2],     ah[mi], bl);
                mma16816(acc[mi][p * 2],     al[mi], bh);
                mma16816(acc[mi][p * 2 + 1], ah[mi], bh + 2);
                mma16816(acc[mi][p * 2 + 1], ah[mi], bl + 2);
                mma16816(acc[mi][p * 2 + 1], al[mi], bh + 2);
            }
        }
        __syncthreads();
    }

    int rbase = row0 + wm * 32 + (lane >> 2);
    int cbase = wn * 64 + (lane & 3) * 2;
#pragma unroll
    for (int mi = 0; mi < 2; mi++)
#pragma unroll
        for (int ni = 0; ni < 8; ni++) {
            int r = rbase + mi * 16;
            int c = cbase + ni * 8;
            if (r < N)
                *(float2*)(C + (size_t)r * 256 + c) = make_float2(acc[mi][ni][0], acc[mi][ni][1]);
            if (r + 8 < N)
                *(float2*)(C + (size_t)(r + 8) * 256 + c) = make_float2(acc[mi][ni][2], acc[mi][ni][3]);
        }

    int hg0 = wn * 2;
    float asr[2][8], adr[2][8];
#pragma unroll
    for (int h = 0; h < 2; h++)
#pragma unroll
        for (int q = 0; q < 4; q++) {
            int c = (hg0 + h) * 32 + q * 8 + (lane & 3) * 2;
            asr[h][q * 2]     = asw[c];
            asr[h][q * 2 + 1] = asw[c + 1];
            adr[h][q * 2]     = adw[c];
            adr[h][q * 2 + 1] = adw[c + 1];
        }
#pragma unroll
    for (int mi = 0; mi < 2; mi++)
#pragma unroll
        for (int half = 0; half < 2; half++) {
            float ps0 = 0.f, pd0 = 0.f, ps1 = 0.f, pd1 = 0.f;
#pragma unroll
            for (int q = 0; q < 4; q++) {
                float v0 = acc[mi][q][half * 2], v1 = acc[mi][q][half * 2 + 1];
                ps0 = fmaf(v0, asr[0][q * 2], ps0); ps0 = fmaf(v1, asr[0][q * 2 + 1], ps0);
                pd0 = fmaf(v0, adr[0][q * 2], pd0); pd0 = fmaf(v1, adr[0][q * 2 + 1], pd0);
                float u0 = acc[mi][4 + q][half * 2], u1 = acc[mi][4 + q][half * 2 + 1];
                ps1 = fmaf(u0, asr[1][q * 2], ps1); ps1 = fmaf(u1, asr[1][q * 2 + 1], ps1);
                pd1 = fmaf(u0, adr[1][q * 2], pd1); pd1 = fmaf(u1, adr[1][q * 2 + 1], pd1);
            }
            ps0 += __shfl_xor_sync(0xffffffffu, ps0, 1); ps0 += __shfl_xor_sync(0xffffffffu, ps0, 2);
            pd0 += __shfl_xor_sync(0xffffffffu, pd0, 1); pd0 += __shfl_xor_sync(0xffffffffu, pd0, 2);
            ps1 += __shfl_xor_sync(0xffffffffu, ps1, 1); ps1 += __shfl_xor_sync(0xffffffffu, ps1, 2);
            pd1 += __shfl_xor_sync(0xffffffffu, pd1, 1); pd1 += __shfl_xor_sync(0xffffffffu, pd1, 2);
            int r = row0 + wm * 32 + mi * 16 + half * 8 + (lane >> 2);
            if ((lane & 3) == 0 && r < N) {
                g_as1[r * HEADS + hg0]     = ps0;
                g_ad1[r * HEADS + hg0]     = pd0;
                g_as1[r * HEADS + hg0 + 1] = ps1;
                g_ad1[r * HEADS + hg0 + 1] = pd1;
            }
        }
}

// ---------------- layer-1 aggregation fused with GEMM2 + att2 ----------------
__global__ void agg1_k(const float* __restrict__ b1, const float* __restrict__ W2,
                       const float* __restrict__ as2w, const float* __restrict__ ad2w,
                       int N) {
    __shared__ float sW2t[NCLS * 256];
    __shared__ float sas2[NCLS], sad2[NCLS];
    int tid = threadIdx.x;
    for (int i = tid; i < 256 * NCLS; i += 256) {
        int c = i >> 4, m = i & 15;
        sW2t[m * 256 + c] = W2[i];
    }
    if (tid < NCLS) { sas2[tid] = as2w[tid]; sad2[tid] = ad2w[tid]; }
    __syncthreads();

    int warp = blockIdx.x * 8 + (tid >> 5);
    if (warp >= N) return;
    int lane = tid & 31;
    int s = g_start[warp], e = g_start[warp + 1];
    float adv = (lane < HEADS) ? g_ad1[warp * HEADS + lane] : 0.f;
    int h0 = lane >> 3;
    bool is_head = (lane < HEADS);

    float4 acc0 = make_float4(0.f, 0.f, 0.f, 0.f);
    float4 acc1 = make_float4(0.f, 0.f, 0.f, 0.f);
    float den = 0.f;

    int i = s;
    for (; i + 3 < e; i += 4) {
        int2 ee[4];
        float asv[4];
        float4 v0[4], v1[4];
#pragma unroll
        for (int u = 0; u < 4; u++) ee[u] = g_csr[i + u];
#pragma unroll
        for (int u = 0; u < 4; u++)
            asv[u] = is_head ? g_as1[ee[u].x * HEADS + lane] : 0.f;
#pragma unroll
        for (int u = 0; u < 4; u++) {
            const float4* hp = (const float4*)(g_h1 + (size_t)ee[u].x * HIDHEAD);
            v0[u] = hp[lane];
            v1[u] = hp[lane + 32];
        }
#pragma unroll
        for (int u = 0; u < 4; u++) {
            float t = 0.f;
            if (is_head) {
                float uu = asv[u] + adv;
                uu = (uu > 0.f ? uu : 0.2f * uu) * __int_as_float(ee[u].y);
                t = __expf(uu);
            }
            den += t;
            float w0 = __shfl_sync(0xffffffffu, t, h0);
            float w1 = __shfl_sync(0xffffffffu, t, 4 + h0);
            acc0.x = fmaf(w0, v0[u].x, acc0.x); acc0.y = fmaf(w0, v0[u].y, acc0.y);
            acc0.z = fmaf(w0, v0[u].z, acc0.z); acc0.w = fmaf(w0, v0[u].w, acc0.w);
            acc1.x = fmaf(w1, v1[u].x, acc1.x); acc1.y = fmaf(w1, v1[u].y, acc1.y);
            acc1.z = fmaf(w1, v1[u].z, acc1.z); acc1.w = fmaf(w1, v1[u].w, acc1.w);
        }
    }
    for (; i < e; i++) {
        int2 ea = g_csr[i];
        float t = 0.f;
        if (is_head) {
            float u = g_as1[ea.x * HEADS + lane] + adv;
            u = (u > 0.f ? u : 0.2f * u) * __int_as_float(ea.y);
            t = __expf(u);
        }
        den += t;
        const float4* hp = (const float4*)(g_h1 + (size_t)ea.x * HIDHEAD);
        float4 va0 = hp[lane], va1 = hp[lane + 32];
        float w0 = __shfl_sync(0xffffffffu, t, h0);
        float w1 = __shfl_sync(0xffffffffu, t, 4 + h0);
        acc0.x = fmaf(w0, va0.x, acc0.x); acc0.y = fmaf(w0, va0.y, acc0.y);
        acc0.z = fmaf(w0, va0.z, acc0.z); acc0.w = fmaf(w0, va0.w, acc0.w);
        acc1.x = fmaf(w1, va1.x, acc1.x); acc1.y = fmaf(w1, va1.y, acc1.y);
        acc1.z = fmaf(w1, va1.z, acc1.z); acc1.w = fmaf(w1, va1.w, acc1.w);
    }

    float d0 = __shfl_sync(0xffffffffu, den, h0);
    float d1 = __shfl_sync(0xffffffffu, den, 4 + h0);
    float inv0 = 1.f / (d0 + 1e-16f);
    float inv1 = 1.f / (d1 + 1e-16f);
    float4 bb0 = ((const float4*)b1)[lane];
    float4 bb1 = ((const float4*)b1)[lane + 32];
    float o[8];
    o[0] = acc0.x * inv0 + bb0.x;  o[1] = acc0.y * inv0 + bb0.y;
    o[2] = acc0.z * inv0 + bb0.z;  o[3] = acc0.w * inv0 + bb0.w;
    o[4] = acc1.x * inv1 + bb1.x;  o[5] = acc1.y * inv1 + bb1.y;
    o[6] = acc1.z * inv1 + bb1.z;  o[7] = acc1.w * inv1 + bb1.w;
#pragma unroll
    for (int j = 0; j < 8; j++) o[j] = (o[j] > 0.f) ? o[j] : (__expf(o[j]) - 1.f);

    float h2p[NCLS];
#pragma unroll
    for (int m = 0; m < NCLS; m++) {
        float4 wv0 = *(const float4*)&sW2t[m * 256 + lane * 4];
        float4 wv1 = *(const float4*)&sW2t[m * 256 + 128 + lane * 4];
        h2p[m] = o[0] * wv0.x + o[1] * wv0.y + o[2] * wv0.z + o[3] * wv0.w
               + o[4] * wv1.x + o[5] * wv1.y + o[6] * wv1.z + o[7] * wv1.w;
    }
#pragma unroll
    for (int off = 16; off >= 1; off >>= 1)
#pragma unroll
        for (int m = 0; m < NCLS; m++)
            h2p[m] += __shfl_xor_sync(0xffffffffu, h2p[m], off);

    float s2 = 0.f, d2 = 0.f;
#pragma unroll
    for (int m = 0; m < NCLS; m++) {
        s2 = fmaf(h2p[m], sas2[m], s2);
        d2 = fmaf(h2p[m], sad2[m], d2);
    }
    if (lane == 0) { g_as2[warp] = s2; g_ad2[warp] = d2; }

    float sel = h2p[0];
#pragma unroll
    for (int m = 1; m < NCLS; m++) sel = (lane == m) ? h2p[m] : sel;
    if (lane < NCLS) g_h2[warp * NCLS + lane] = sel;
}

// ---------------- layer-2 softmax aggregation ----------------
__global__ void agg2_k(const float* __restrict__ b2, float* __restrict__ out, int N) {
    int warp = (blockIdx.x * blockDim.x + threadIdx.x) >> 5;
    if (warp >= N) return;
    int lane = threadIdx.x & 31;
    int s = g_start[warp], e = g_start[warp + 1];
    float adv = g_ad2[warp];
    bool lo = (lane < NCLS);

    float acc = 0.f, den = 0.f;
    int i = s;
    for (; i + 3 < e; i += 4) {
        int2 ee[4];
        float lg[4], fv[4];
#pragma unroll
        for (int u = 0; u < 4; u++) ee[u] = g_csr[i + u];
#pragma unroll
        for (int u = 0; u < 4; u++) lg[u] = g_as2[ee[u].x] + adv;
#pragma unroll
        for (int u = 0; u < 4; u++)
            fv[u] = lo ? g_h2[(size_t)ee[u].x * NCLS + lane] : 0.f;
#pragma unroll
        for (int u = 0; u < 4; u++) {
            float t = (lg[u] > 0.f ? lg[u] : 0.2f * lg[u]) * __int_as_float(ee[u].y);
            float x = __expf(t);
            den += x;
            acc = fmaf(x, fv[u], acc);
        }
    }
    for (; i < e; i++) {
        int2 ea = g_csr[i];
        float la = g_as2[ea.x] + adv;
        la = (la > 0.f ? la : 0.2f * la) * __int_as_float(ea.y);
        float xa = __expf(la);
        den += xa;
        if (lo) acc = fmaf(xa, g_h2[(size_t)ea.x * NCLS + lane], acc);
    }
    if (lo) out[(size_t)warp * NCLS + lane] = acc / (den + 1e-16f) + b2[lane];
}

// ---------------- launch ----------------
extern "C" void kernel_launch(void* const* d_in, const int* in_sizes, int n_in,
                              void* d_out, int out_size) {
    const float* x   = (const float*)d_in[0];
    const int*   ei  = (const int*)  d_in[1];
    const float* ew  = (const float*)d_in[2];
    const float* W1  = (const float*)d_in[3];
    const float* as1 = (const float*)d_in[4];
    const float* ad1 = (const float*)d_in[5];
    const float* b1  = (const float*)d_in[6];
    const float* W2  = (const float*)d_in[7];
    const float* as2 = (const float*)d_in[8];
    const float* ad2 = (const float*)d_in[9];
    const float* b2  = (const float*)d_in[10];
    float* out = (float*)d_out;

    int N  = in_sizes[0] / IN_CH;
    int E  = in_sizes[2];
    int ET = E + N;

    float *h1;
    void *degp, *xh, *xl, *wh, *wl;
    cudaGetSymbolAddress((void**)&h1, g_h1);
    cudaGetSymbolAddress(&degp, g_deg);
    cudaGetSymbolAddress(&xh, g_xh);
    cudaGetSymbolAddress(&xl, g_xl);
    cudaGetSymbolAddress(&wh, g_wh);
    cudaGetSymbolAddress(&wl, g_wl);

    // hi/lo split conversion
    int n4w = (IN_CH * HIDHEAD) / 4;
    conv_k<<<(n4w + 255) / 256, 256>>>((const float4*)W1, (uint2*)wh, (uint2*)wl, n4w);
    int n4x = (N * IN_CH) / 4;
    conv_k<<<(n4x + 255) / 256, 256>>>((const float4*)x, (uint2*)xh, (uint2*)xl, n4x);

    // CSR build (parallel 3-phase scan)
    cudaMemsetAsync(degp, 0, (size_t)N * sizeof(int));
    hist_k<<<(ET + 255) / 256, 256>>>(ei, E, ET);
    scanA_k<<<NBLK, SCAN_B>>>(N);
    scanB_k<<<1, 64>>>(N);
    scanC_k<<<NBLK, SCAN_B>>>(N);
    scatter_k<<<(ET + 255) / 256, 256>>>(ei, ew, E, ET);

    // layer 1 GEMM (tensor core, cp.async 4-stage) + att1 fused
    {
        const int SMEM = 114688;
        cudaFuncSetAttribute(mma_gemm_att_k, cudaFuncAttributeMaxDynamicSharedMemorySize, SMEM);
        mma_gemm_att_k<<<(N + 127) / 128, 512, SMEM>>>(
            (const __nv_bfloat16*)xh, (const __nv_bfloat16*)xl,
            (const __nv_bfloat16*)wh, (const __nv_bfloat16*)wl,
            h1, as1, ad1, N);
    }
    agg1_k<<<(N + 7) / 8, 256>>>(b1, W2, as2, ad2, N);

    // layer 2
    agg2_k<<<(N + 7) / 8, 256>>>(b2, out, N);
}